// round 11
// baseline (speedup 1.0000x reference)
#include <cuda_runtime.h>
#include <cuda_fp16.h>
#include <cstdint>

// Problem constants
#define BATCH 16
#define HH 56
#define WW 56
#define NN (HH * WW)          // 3136
#define CC 384
#define C3 (3 * CC)           // 1152
#define NHEADS 12
#define HD 32
#define WSZ 7
#define WIN 49
#define MROWS (BATCH * NN)    // 50176

// GEMM tiling (fp16): 128x128x32 CTA tile, 4 warps of 64x64
#define BM 128
#define BN 128
#define BK 32
#define SROWH 40                  // smem row stride in halves (80B, conflict-free)
#define ABUF (BM * SROWH * 2)     // 10240 bytes per buffer
#define STAGE_BYTES (2 * ABUF)    // 20480
#define NSTAGE 4

// Attention smem geometry: per head Q,K,V tiles of 64 rows x 80B
#define ATILE 5120
#define AHEAD (3 * ATILE)
#define ASMEM (4 * AHEAD)         // 61440

// Scratch (allocation-free rule: __device__ globals)
__device__ __half g_qkvh[(size_t)MROWS * C3];   // 115.5 MB
__device__ __half g_xh[(size_t)MROWS * CC];     // 38.5 MB
__device__ __half g_yh[(size_t)MROWS * CC];     // 38.5 MB
__device__ __half g_wt1[(size_t)C3 * CC];       // w_qkv^T fp16
__device__ __half g_wt2[(size_t)CC * CC];       // w_proj^T fp16

// ---------------------------------------------------------------------------
__device__ __forceinline__ uint32_t smem_u32(const void* p) {
    uint32_t a;
    asm("{ .reg .u64 t; cvta.to.shared.u64 t, %1; cvt.u32.u64 %0, t; }" : "=r"(a) : "l"(p));
    return a;
}
__device__ __forceinline__ void cp_async16(uint32_t saddr, const void* gaddr) {
    asm volatile("cp.async.cg.shared.global [%0], [%1], 16;" :: "r"(saddr), "l"(gaddr));
}
template <int N>
__device__ __forceinline__ void cp_wait() {
    asm volatile("cp.async.wait_group %0;" :: "n"(N) : "memory");
}
__device__ __forceinline__ void mma_f16(float c[4], const uint32_t a[4],
                                        uint32_t b0, uint32_t b1) {
    asm volatile(
        "mma.sync.aligned.m16n8k16.row.col.f32.f16.f16.f32 "
        "{%0,%1,%2,%3}, {%4,%5,%6,%7}, {%8,%9}, {%0,%1,%2,%3};"
        : "+f"(c[0]), "+f"(c[1]), "+f"(c[2]), "+f"(c[3])
        : "r"(a[0]), "r"(a[1]), "r"(a[2]), "r"(a[3]), "r"(b0), "r"(b1));
}
__device__ __forceinline__ void ldm_x4(uint32_t r[4], uint32_t addr) {
    asm volatile("ldmatrix.sync.aligned.m8n8.x4.shared.b16 {%0,%1,%2,%3}, [%4];"
        : "=r"(r[0]), "=r"(r[1]), "=r"(r[2]), "=r"(r[3]) : "r"(addr));
}
__device__ __forceinline__ void ldm_x4_t(uint32_t r[4], uint32_t addr) {
    asm volatile("ldmatrix.sync.aligned.m8n8.x4.trans.shared.b16 {%0,%1,%2,%3}, [%4];"
        : "=r"(r[0]), "=r"(r[1]), "=r"(r[2]), "=r"(r[3]) : "r"(addr));
}
__device__ __forceinline__ uint32_t h2u(__half2 h) {
    return *reinterpret_cast<uint32_t*>(&h);
}

// ---------------------------------------------------------------------------
// fp16 mma.sync GEMM: C[M,N] = A[M,K] @ Bt[N,K]^T (+bias for fp32 out).
// 128 threads, 4 warps (2m x 2n), 64x64 per warp. 4-stage cp.async, BK=32.
// ---------------------------------------------------------------------------
template <bool HALF_OUT>
__global__ __launch_bounds__(128, 2)
void gemm_f16_kernel(const __half* __restrict__ A, const __half* __restrict__ Bt,
                     void* __restrict__ Cout, const float* __restrict__ bias,
                     int M, int N, int K)
{
    extern __shared__ char smem[];
    const uint32_t sbase = smem_u32(smem);

    const int tid  = threadIdx.x;
    const int wid  = tid >> 5;
    const int lane = tid & 31;
    const int wm = (wid & 1) * 64;
    const int wn = (wid >> 1) * 64;
    const int qr = lane >> 2;
    const int qc = lane & 3;

    const int nbase = blockIdx.x * BN;
    const size_t mbase = (size_t)blockIdx.y * BM;

    // loader: one thread per row, 4 chunks A + 4 chunks B
    const int row_ld = tid;

    // ldmatrix per-lane offsets (g=lane>>3 selects quadrant of x4)
    const int r8  = lane & 7;
    const int sel = lane >> 3;
    const uint32_t rowadd = (uint32_t)((sel & 1) << 3);
    const uint32_t kbadd  = (uint32_t)((sel >> 1) << 4);
    uint32_t a_off[4], b_off[4];
    #pragma unroll
    for (int i = 0; i < 4; i++)
        a_off[i] = (uint32_t)(wm + 16 * i + rowadd + r8) * (SROWH * 2) + kbadd;
    #pragma unroll
    for (int p = 0; p < 4; p++)
        b_off[p] = (uint32_t)ABUF
                 + (uint32_t)(wn + 16 * p + rowadd + r8) * (SROWH * 2) + kbadd;

    float acc[4][8][4];
    #pragma unroll
    for (int i = 0; i < 4; i++)
        #pragma unroll
        for (int j = 0; j < 8; j++)
            #pragma unroll
            for (int t = 0; t < 4; t++) acc[i][j][t] = 0.f;

    const int nstages = K / BK;

    auto load_stage = [&](int s) {
        const uint32_t base = sbase + (uint32_t)(s % NSTAGE) * STAGE_BYTES;
        const int k0 = s * BK;
        const __half* Ag = A + (mbase + row_ld) * (size_t)K + k0;
        const __half* Bg = Bt + (size_t)(nbase + row_ld) * K + k0;
        const uint32_t soff = (uint32_t)row_ld * (SROWH * 2);
        #pragma unroll
        for (int ch = 0; ch < 4; ch++) {
            cp_async16(base + soff + ((uint32_t)ch << 4), Ag + (ch << 3));
            cp_async16(base + ABUF + soff + ((uint32_t)ch << 4), Bg + (ch << 3));
        }
        asm volatile("cp.async.commit_group;");
    };

    load_stage(0);
    load_stage(1);
    load_stage(2);

    for (int s = 0; s < nstages; s++) {
        if      (s + 2 < nstages) cp_wait<2>();
        else if (s + 1 < nstages) cp_wait<1>();
        else                      cp_wait<0>();
        __syncthreads();
        if (s + 3 < nstages) load_stage(s + 3);

        const uint32_t sstage = sbase + (uint32_t)(s % NSTAGE) * STAGE_BYTES;
        #pragma unroll
        for (int ks = 0; ks < 2; ks++) {
            const uint32_t kb = (uint32_t)ks << 5;     // k-step = 32 bytes
            uint32_t afr[4][4];
            uint32_t bfr[4][4];
            #pragma unroll
            for (int i = 0; i < 4; i++) ldm_x4(afr[i], sstage + a_off[i] + kb);
            #pragma unroll
            for (int p = 0; p < 4; p++) ldm_x4(bfr[p], sstage + b_off[p] + kb);
            #pragma unroll
            for (int i = 0; i < 4; i++)
                #pragma unroll
                for (int j = 0; j < 8; j++)
                    mma_f16(acc[i][j], afr[i], bfr[j >> 1][j & 1],
                            bfr[j >> 1][(j & 1) + 2]);
        }
    }

    // Epilogue
    #pragma unroll
    for (int i = 0; i < 4; i++) {
        const size_t row = mbase + wm + i * 16 + qr;
        #pragma unroll
        for (int j = 0; j < 8; j++) {
            const int col = nbase + wn + j * 8 + 2 * qc;
            if (HALF_OUT) {
                __half* Ch = (__half*)Cout;
                *(__half2*)(Ch + row * (size_t)N + col) =
                    __floats2half2_rn(acc[i][j][0], acc[i][j][1]);
                *(__half2*)(Ch + (row + 8) * (size_t)N + col) =
                    __floats2half2_rn(acc[i][j][2], acc[i][j][3]);
            } else {
                float* Cf = (float*)Cout;
                float2 v0 = make_float2(acc[i][j][0], acc[i][j][1]);
                float2 v1 = make_float2(acc[i][j][2], acc[i][j][3]);
                if (bias) {
                    float2 bb = *(const float2*)(bias + col);
                    v0.x += bb.x; v0.y += bb.y;
                    v1.x += bb.x; v1.y += bb.y;
                }
                *(float2*)(Cf + row * (size_t)N + col) = v0;
                *(float2*)(Cf + (row + 8) * (size_t)N + col) = v1;
            }
        }
    }
}

// ---------------------------------------------------------------------------
__global__ void to_half_kernel(const float* __restrict__ in, __half* __restrict__ out, int n4)
{
    int i = blockIdx.x * blockDim.x + threadIdx.x;
    if (i >= n4) return;
    float4 v = ((const float4*)in)[i];
    ((__half2*)out)[i * 2 + 0] = __floats2half2_rn(v.x, v.y);
    ((__half2*)out)[i * 2 + 1] = __floats2half2_rn(v.z, v.w);
}

__global__ void transpose_half_kernel(const float* __restrict__ in, __half* __restrict__ out,
                                      int K, int N)
{
    int i = blockIdx.x * blockDim.x + threadIdx.x;
    if (i >= K * N) return;
    int n = i % N, k = i / N;
    out[(size_t)n * K + k] = __float2half_rn(in[(size_t)k * N + n]);
}

// ---------------------------------------------------------------------------
// Tensor-core windowed attention (validated R10). Block = (b, window,
// headgroup of 4), 128 threads, warp w handles one head.
// ---------------------------------------------------------------------------
__global__ __launch_bounds__(128)
void attn_tc_kernel(const __half* __restrict__ qkvh, __half* __restrict__ yh)
{
    extern __shared__ char sm[];
    const uint32_t sbase = smem_u32(sm);
    const int tid  = threadIdx.x;
    const int wid  = tid >> 5;
    const int lane = tid & 31;
    const int qr = lane >> 2, qc = lane & 3;
    const int r8 = lane & 7, g = lane >> 3;

    int blk = blockIdx.x;
    const int hg = blk % 3; blk /= 3;
    const int w = blk & 63; const int b = blk >> 6;
    const int row0 = (w >> 3) * 7, cpix0 = (w & 7) * 7;
    const int col0 = (hg * 4 + wid) * HD;

    {
        const uint4 z = make_uint4(0, 0, 0, 0);
        for (int t = tid; t < 720; t += 128) {
            int c = t & 3, r = (t >> 2) % 15, zt = t / 60;
            *(uint4*)(sm + zt * ATILE + (49 + r) * 80 + c * 16) = z;
        }
    }
    for (int it = 0; it < 19; it++) {
        int idx = tid + it * 128;
        if (idx < 2352) {
            int c = idx & 3;
            int r = (idx >> 2) % 49;
            int zt = (idx >> 2) / 49;
            int hh = zt / 3, tz = zt % 3;
            int pix = (row0 + r / 7) * WW + cpix0 + (r % 7);
            const __half* src = qkvh + ((size_t)(b * NN + pix)) * C3
                              + tz * CC + (hg * 4 + hh) * HD + c * 8;
            cp_async16(sbase + (uint32_t)(zt * ATILE + r * 80 + c * 16), src);
        }
    }
    asm volatile("cp.async.commit_group;");
    cp_wait<0>();
    __syncthreads();

    const uint32_t QB = sbase + (uint32_t)(wid * AHEAD);
    const uint32_t KB = QB + ATILE;
    const uint32_t VB = QB + 2 * ATILE;

    uint32_t Kf[8][2][2];
    #pragma unroll
    for (int up = 0; up < 4; up++)
        #pragma unroll
        for (int s = 0; s < 2; s++) {
            uint32_t addr = KB + (uint32_t)(16 * up + r8 + ((g & 1) << 3)) * 80u
                          + (uint32_t)(32 * s + ((g >> 1) << 4));
            uint32_t r[4];
            ldm_x4(r, addr);
            Kf[2 * up][s][0] = r[0]; Kf[2 * up][s][1] = r[2];
            Kf[2 * up + 1][s][0] = r[1]; Kf[2 * up + 1][s][1] = r[3];
        }
    uint32_t Vf[4][4][2];
    #pragma unroll
    for (int wk = 0; wk < 4; wk++)
        #pragma unroll
        for (int up = 0; up < 2; up++) {
            uint32_t addr = VB + (uint32_t)(16 * wk + r8 + ((g >> 1) << 3)) * 80u
                          + (uint32_t)(32 * up + ((g & 1) << 4));
            uint32_t r[4];
            ldm_x4_t(r, addr);
            Vf[2 * up][wk][0] = r[0]; Vf[2 * up][wk][1] = r[2];
            Vf[2 * up + 1][wk][0] = r[1]; Vf[2 * up + 1][wk][1] = r[3];
        }

    bool vc0[7], vc1[7];
    #pragma unroll
    for (int u = 0; u < 7; u++) {
        int cb = 8 * u + 2 * qc;
        vc0[u] = cb < WIN;
        vc1[u] = cb + 1 < WIN;
    }

    const float scale = 0.17677669529663687f;

    #pragma unroll
    for (int t = 0; t < 4; t++) {
        uint32_t Qf[2][4];
        #pragma unroll
        for (int s = 0; s < 2; s++) {
            uint32_t addr = QB + (uint32_t)(16 * t + r8 + ((g & 1) << 3)) * 80u
                          + (uint32_t)(32 * s + ((g >> 1) << 4));
            ldm_x4(Qf[s], addr);
        }
        float S[7][4];
        #pragma unroll
        for (int u = 0; u < 7; u++) {
            S[u][0] = S[u][1] = S[u][2] = S[u][3] = 0.f;
            mma_f16(S[u], Qf[0], Kf[u][0][0], Kf[u][0][1]);
            mma_f16(S[u], Qf[1], Kf[u][1][0], Kf[u][1][1]);
        }

        const int rr0 = 16 * t + qr;
        const int rr1 = rr0 + 8;
        const bool vr0 = rr0 < WIN, vr1 = rr1 < WIN;

        float m0 = -1e30f, m1 = -1e30f;
        #pragma unroll
        for (int u = 0; u < 7; u++) {
            if (vc0[u]) { m0 = fmaxf(m0, S[u][0]); m1 = fmaxf(m1, S[u][2]); }
            if (vc1[u]) { m0 = fmaxf(m0, S[u][1]); m1 = fmaxf(m1, S[u][3]); }
        }
        #pragma unroll
        for (int o = 1; o <= 2; o <<= 1) {
            m0 = fmaxf(m0, __shfl_xor_sync(0xffffffffu, m0, o));
            m1 = fmaxf(m1, __shfl_xor_sync(0xffffffffu, m1, o));
        }

        uint32_t P[8][2];
        P[7][0] = 0u; P[7][1] = 0u;
        float sum0 = 0.f, sum1 = 0.f;
        #pragma unroll
        for (int u = 0; u < 7; u++) {
            float p0 = 0.f, p1 = 0.f, p2 = 0.f, p3 = 0.f;
            if (vr0) {
                if (vc0[u]) p0 = __expf((S[u][0] - m0) * scale);
                if (vc1[u]) p1 = __expf((S[u][1] - m0) * scale);
            }
            if (vr1) {
                if (vc0[u]) p2 = __expf((S[u][2] - m1) * scale);
                if (vc1[u]) p3 = __expf((S[u][3] - m1) * scale);
            }
            sum0 += p0 + p1;
            sum1 += p2 + p3;
            P[u][0] = h2u(__floats2half2_rn(p0, p1));
            P[u][1] = h2u(__floats2half2_rn(p2, p3));
        }
        #pragma unroll
        for (int o = 1; o <= 2; o <<= 1) {
            sum0 += __shfl_xor_sync(0xffffffffu, sum0, o);
            sum1 += __shfl_xor_sync(0xffffffffu, sum1, o);
        }
        const float is0 = vr0 ? 1.f / sum0 : 0.f;
        const float is1 = vr1 ? 1.f / sum1 : 0.f;

        float O[4][4];
        #pragma unroll
        for (int u = 0; u < 4; u++)
            O[u][0] = O[u][1] = O[u][2] = O[u][3] = 0.f;
        #pragma unroll
        for (int wk = 0; wk < 4; wk++) {
            uint32_t afr[4] = { P[2 * wk][0], P[2 * wk][1],
                                P[2 * wk + 1][0], P[2 * wk + 1][1] };
            #pragma unroll
            for (int u = 0; u < 4; u++)
                mma_f16(O[u], afr, Vf[u][wk][0], Vf[u][wk][1]);
        }

        if (vr0) {
            int pix = (row0 + rr0 / 7) * WW + cpix0 + (rr0 % 7);
            __half* base = yh + ((size_t)(b * NN + pix)) * CC + col0;
            #pragma unroll
            for (int u = 0; u < 4; u++)
                *(__half2*)(base + 8 * u + 2 * qc) =
                    __floats2half2_rn(O[u][0] * is0, O[u][1] * is0);
        }
        if (vr1) {
            int pix = (row0 + rr1 / 7) * WW + cpix0 + (rr1 % 7);
            __half* base = yh + ((size_t)(b * NN + pix)) * CC + col0;
            #pragma unroll
            for (int u = 0; u < 4; u++)
                *(__half2*)(base + 8 * u + 2 * qc) =
                    __floats2half2_rn(O[u][2] * is1, O[u][3] * is1);
        }
    }
}

// ---------------------------------------------------------------------------
// Depthwise 3x3 conv on v (fp16) + bias, accumulated into yh (fp16 rmw).
// ---------------------------------------------------------------------------
__global__ __launch_bounds__(256)
void conv_add_h_kernel(const __half* __restrict__ qkvh,
                       const float* __restrict__ w_conv,
                       const float* __restrict__ b_conv,
                       __half* __restrict__ yh)
{
    const int CG = CC / 8;  // 48
    int idx = blockIdx.x * blockDim.x + threadIdx.x;
    if (idx >= BATCH * NN * CG) return;
    int cg = idx % CG;
    int n = (idx / CG) % NN;
    int b = idx / (CG * NN);
    int hh = n / WW, ww = n % WW;
    const int c = cg * 8;

    float acc[8];
    #pragma unroll
    for (int e = 0; e < 8; e++) acc[e] = b_conv[c + e];

    #pragma unroll
    for (int kh = 0; kh < 3; kh++) {
        int hn = hh + kh - 1;
        if ((unsigned)hn >= (unsigned)HH) continue;
        #pragma unroll
        for (int kw = 0; kw < 3; kw++) {
            int wn = ww + kw - 1;
            if ((unsigned)wn >= (unsigned)WW) continue;
            uint4 vr = *(const uint4*)(qkvh + ((size_t)(b * NN + hn * WW + wn)) * C3
                                       + 2 * CC + c);
            const __half2* v2 = (const __half2*)&vr;
            const float* wc = w_conv + (kh * 3 + kw) * CC + c;
            #pragma unroll
            for (int e = 0; e < 4; e++) {
                float2 vf = __half22float2(v2[e]);
                acc[e * 2 + 0] += vf.x * wc[e * 2 + 0];
                acc[e * 2 + 1] += vf.y * wc[e * 2 + 1];
            }
        }
    }

    __half* yo = yh + ((size_t)(b * NN + n)) * CC + c;
    uint4 yv = *(uint4*)yo;
    __half2* y2 = (__half2*)&yv;
    #pragma unroll
    for (int e = 0; e < 4; e++) {
        float2 yf = __half22float2(y2[e]);
        y2[e] = __floats2half2_rn(yf.x + acc[e * 2], yf.y + acc[e * 2 + 1]);
    }
    *(uint4*)yo = yv;
}

// ---------------------------------------------------------------------------
extern "C" void kernel_launch(void* const* d_in, const int* in_sizes, int n_in,
                              void* d_out, int out_size)
{
    const float* x      = (const float*)d_in[0];
    const float* w_qkv  = (const float*)d_in[1];
    const float* w_proj = (const float*)d_in[2];
    const float* b_proj = (const float*)d_in[3];
    const float* w_conv = (const float*)d_in[4];
    const float* b_conv = (const float*)d_in[5];
    float* out = (float*)d_out;

    __half *qkvh_p, *xh_p, *yh_p, *wt1_p, *wt2_p;
    cudaGetSymbolAddress((void**)&qkvh_p, g_qkvh);
    cudaGetSymbolAddress((void**)&xh_p, g_xh);
    cudaGetSymbolAddress((void**)&yh_p, g_yh);
    cudaGetSymbolAddress((void**)&wt1_p, g_wt1);
    cudaGetSymbolAddress((void**)&wt2_p, g_wt2);

    const int gemm_smem = NSTAGE * STAGE_BYTES;  // 81920
    cudaFuncSetAttribute(gemm_f16_kernel<true>,
                         cudaFuncAttributeMaxDynamicSharedMemorySize, gemm_smem);
    cudaFuncSetAttribute(gemm_f16_kernel<false>,
                         cudaFuncAttributeMaxDynamicSharedMemorySize, gemm_smem);
    cudaFuncSetAttribute(attn_tc_kernel,
                         cudaFuncAttributeMaxDynamicSharedMemorySize, ASMEM);

    // 0) fp16 conversions
    {
        int n4 = MROWS * CC / 4;
        to_half_kernel<<<(n4 + 255) / 256, 256>>>(x, xh_p, n4);
        transpose_half_kernel<<<(CC * C3 + 255) / 256, 256>>>(w_qkv, wt1_p, CC, C3);
        transpose_half_kernel<<<(CC * CC + 255) / 256, 256>>>(w_proj, wt2_p, CC, CC);
    }
    // 1) qkvh = x @ w_qkv (fp16 out)
    {
        dim3 grid(C3 / BN, MROWS / BM);
        gemm_f16_kernel<true><<<grid, 128, gemm_smem>>>(xh_p, wt1_p, qkvh_p, nullptr,
                                                        MROWS, C3, CC);
    }
    // 2) tensor-core windowed attention -> yh (fp16)
    attn_tc_kernel<<<BATCH * 64 * 3, 128, ASMEM>>>(qkvh_p, yh_p);
    // 3) yh += depthwise conv3x3(v) + b_conv
    {
        int total = BATCH * NN * (CC / 8);
        conv_add_h_kernel<<<(total + 255) / 256, 256>>>(qkvh_p, w_conv, b_conv, yh_p);
    }
    // 4) out = yh @ w_proj + b_proj (fp32 out)
    {
        dim3 grid(CC / BN, MROWS / BM);
        gemm_f16_kernel<false><<<grid, 128, gemm_smem>>>(yh_p, wt2_p, out, b_proj,
                                                         MROWS, CC, CC);
    }
}

// round 12
// speedup vs baseline: 1.1414x; 1.1414x over previous
#include <cuda_runtime.h>
#include <cuda_fp16.h>
#include <cstdint>

// Problem constants
#define BATCH 16
#define HH 56
#define WW 56
#define NN (HH * WW)          // 3136
#define CC 384
#define C3 (3 * CC)           // 1152
#define NHEADS 12
#define HD 32
#define WSZ 7
#define WIN 49
#define MROWS (BATCH * NN)    // 50176

// GEMM tiling (fp16): 128x128x32 CTA tile, 8 warps of 64x32 (R10 optimum)
#define BM 128
#define BN 128
#define BK 32
#define SROWH 40                  // smem row stride in halves (80B, conflict-free)
#define ABUF (BM * SROWH * 2)     // 10240 bytes per buffer
#define STAGE_BYTES (2 * ABUF)    // 20480
#define NSTAGE 4

// Attention smem: per head Q,K,V tiles of 49 rows x 80B (masking handles tails)
#define ATILE 3920                // 49 * 80
#define AHEAD (3 * ATILE)         // 11760
#define ASMEM (4 * AHEAD)         // 47040

// Scratch (allocation-free rule: __device__ globals)
__device__ __half g_qkvh[(size_t)MROWS * C3];   // 115.5 MB
__device__ __half g_xh[(size_t)MROWS * CC];     // 38.5 MB
__device__ __half g_yh[(size_t)MROWS * CC];     // 38.5 MB
__device__ __half g_wt1[(size_t)C3 * CC];       // w_qkv^T fp16
__device__ __half g_wt2[(size_t)CC * CC];       // w_proj^T fp16

// ---------------------------------------------------------------------------
__device__ __forceinline__ uint32_t smem_u32(const void* p) {
    uint32_t a;
    asm("{ .reg .u64 t; cvta.to.shared.u64 t, %1; cvt.u32.u64 %0, t; }" : "=r"(a) : "l"(p));
    return a;
}
__device__ __forceinline__ void cp_async16(uint32_t saddr, const void* gaddr) {
    asm volatile("cp.async.cg.shared.global [%0], [%1], 16;" :: "r"(saddr), "l"(gaddr));
}
template <int N>
__device__ __forceinline__ void cp_wait() {
    asm volatile("cp.async.wait_group %0;" :: "n"(N) : "memory");
}
__device__ __forceinline__ void mma_f16(float c[4], const uint32_t a[4],
                                        uint32_t b0, uint32_t b1) {
    asm volatile(
        "mma.sync.aligned.m16n8k16.row.col.f32.f16.f16.f32 "
        "{%0,%1,%2,%3}, {%4,%5,%6,%7}, {%8,%9}, {%0,%1,%2,%3};"
        : "+f"(c[0]), "+f"(c[1]), "+f"(c[2]), "+f"(c[3])
        : "r"(a[0]), "r"(a[1]), "r"(a[2]), "r"(a[3]), "r"(b0), "r"(b1));
}
__device__ __forceinline__ void ldm_x4(uint32_t r[4], uint32_t addr) {
    asm volatile("ldmatrix.sync.aligned.m8n8.x4.shared.b16 {%0,%1,%2,%3}, [%4];"
        : "=r"(r[0]), "=r"(r[1]), "=r"(r[2]), "=r"(r[3]) : "r"(addr));
}
__device__ __forceinline__ void ldm_x4_t(uint32_t r[4], uint32_t addr) {
    asm volatile("ldmatrix.sync.aligned.m8n8.x4.trans.shared.b16 {%0,%1,%2,%3}, [%4];"
        : "=r"(r[0]), "=r"(r[1]), "=r"(r[2]), "=r"(r[3]) : "r"(addr));
}
__device__ __forceinline__ uint32_t h2u(__half2 h) {
    return *reinterpret_cast<uint32_t*>(&h);
}

// ---------------------------------------------------------------------------
// fp16 mma.sync GEMM (R10 optimum): 256 thr, 8 warps (2m x 4n), 64x32/warp.
// ---------------------------------------------------------------------------
template <bool HALF_OUT>
__global__ __launch_bounds__(256, 2)
void gemm_f16_kernel(const __half* __restrict__ A, const __half* __restrict__ Bt,
                     void* __restrict__ Cout, const float* __restrict__ bias,
                     int M, int N, int K)
{
    extern __shared__ char smem[];
    const uint32_t sbase = smem_u32(smem);

    const int tid  = threadIdx.x;
    const int wid  = tid >> 5;
    const int lane = tid & 31;
    const int wm = (wid & 1) * 64;
    const int wn = (wid >> 1) * 32;
    const int qr = lane >> 2;
    const int qc = lane & 3;

    const int nbase = blockIdx.x * BN;
    const size_t mbase = (size_t)blockIdx.y * BM;

    const int row_ld = tid >> 1;
    const int c2_ld  = (tid & 1) << 1;

    const int r8  = lane & 7;
    const int sel = lane >> 3;
    const uint32_t rowadd = (uint32_t)((sel & 1) << 3);
    const uint32_t kbadd  = (uint32_t)((sel >> 1) << 4);
    uint32_t a_off[4], b_off[2];
    #pragma unroll
    for (int i = 0; i < 4; i++)
        a_off[i] = (uint32_t)(wm + 16 * i + rowadd + r8) * (SROWH * 2) + kbadd;
    #pragma unroll
    for (int p = 0; p < 2; p++)
        b_off[p] = (uint32_t)ABUF
                 + (uint32_t)(wn + 16 * p + rowadd + r8) * (SROWH * 2) + kbadd;

    float acc[4][4][4];
    #pragma unroll
    for (int i = 0; i < 4; i++)
        #pragma unroll
        for (int j = 0; j < 4; j++)
            #pragma unroll
            for (int t = 0; t < 4; t++) acc[i][j][t] = 0.f;

    const int nstages = K / BK;

    auto load_stage = [&](int s) {
        const uint32_t base = sbase + (uint32_t)(s % NSTAGE) * STAGE_BYTES;
        const int k0 = s * BK;
        const __half* Ag = A + (mbase + row_ld) * (size_t)K + k0;
        const __half* Bg = Bt + (size_t)(nbase + row_ld) * K + k0;
        const uint32_t soff = (uint32_t)row_ld * (SROWH * 2);
        #pragma unroll
        for (int cc = 0; cc < 2; cc++) {
            const int ch = c2_ld + cc;
            cp_async16(base + soff + ((uint32_t)ch << 4), Ag + (ch << 3));
            cp_async16(base + ABUF + soff + ((uint32_t)ch << 4), Bg + (ch << 3));
        }
        asm volatile("cp.async.commit_group;");
    };

    load_stage(0);
    load_stage(1);
    load_stage(2);

    for (int s = 0; s < nstages; s++) {
        if      (s + 2 < nstages) cp_wait<2>();
        else if (s + 1 < nstages) cp_wait<1>();
        else                      cp_wait<0>();
        __syncthreads();
        if (s + 3 < nstages) load_stage(s + 3);

        const uint32_t sstage = sbase + (uint32_t)(s % NSTAGE) * STAGE_BYTES;
        #pragma unroll
        for (int ks = 0; ks < 2; ks++) {
            const uint32_t kb = (uint32_t)ks << 5;
            uint32_t afr[4][4];
            uint32_t bfr[2][4];
            #pragma unroll
            for (int i = 0; i < 4; i++) ldm_x4(afr[i], sstage + a_off[i] + kb);
            #pragma unroll
            for (int p = 0; p < 2; p++) ldm_x4(bfr[p], sstage + b_off[p] + kb);
            #pragma unroll
            for (int i = 0; i < 4; i++)
                #pragma unroll
                for (int j = 0; j < 4; j++)
                    mma_f16(acc[i][j], afr[i], bfr[j >> 1][j & 1],
                            bfr[j >> 1][(j & 1) + 2]);
        }
    }

    #pragma unroll
    for (int i = 0; i < 4; i++) {
        const size_t row = mbase + wm + i * 16 + qr;
        #pragma unroll
        for (int j = 0; j < 4; j++) {
            const int col = nbase + wn + j * 8 + 2 * qc;
            if (HALF_OUT) {
                __half* Ch = (__half*)Cout;
                *(__half2*)(Ch + row * (size_t)N + col) =
                    __floats2half2_rn(acc[i][j][0], acc[i][j][1]);
                *(__half2*)(Ch + (row + 8) * (size_t)N + col) =
                    __floats2half2_rn(acc[i][j][2], acc[i][j][3]);
            } else {
                float* Cf = (float*)Cout;
                float2 v0 = make_float2(acc[i][j][0], acc[i][j][1]);
                float2 v1 = make_float2(acc[i][j][2], acc[i][j][3]);
                if (bias) {
                    float2 bb = *(const float2*)(bias + col);
                    v0.x += bb.x; v0.y += bb.y;
                    v1.x += bb.x; v1.y += bb.y;
                }
                *(float2*)(Cf + row * (size_t)N + col) = v0;
                *(float2*)(Cf + (row + 8) * (size_t)N + col) = v1;
            }
        }
    }
}

// ---------------------------------------------------------------------------
__global__ void to_half_kernel(const float* __restrict__ in, __half* __restrict__ out, int n4)
{
    int i = blockIdx.x * blockDim.x + threadIdx.x;
    if (i >= n4) return;
    float4 v = ((const float4*)in)[i];
    ((__half2*)out)[i * 2 + 0] = __floats2half2_rn(v.x, v.y);
    ((__half2*)out)[i * 2 + 1] = __floats2half2_rn(v.z, v.w);
}

__global__ void transpose_half_kernel(const float* __restrict__ in, __half* __restrict__ out,
                                      int K, int N)
{
    int i = blockIdx.x * blockDim.x + threadIdx.x;
    if (i >= K * N) return;
    int n = i % N, k = i / N;
    out[(size_t)n * K + k] = __float2half_rn(in[(size_t)k * N + n]);
}

// ---------------------------------------------------------------------------
// Tensor-core windowed attention, 49-row tiles + clamped ldmatrix rows
// (masking makes out-of-range data harmless; clamping keeps reads in-bounds).
// Block = (b, window, headgroup of 4), 128 threads, warp = one head.
// ---------------------------------------------------------------------------
__global__ __launch_bounds__(128)
void attn_tc_kernel(const __half* __restrict__ qkvh, __half* __restrict__ yh)
{
    extern __shared__ char sm[];
    const uint32_t sbase = smem_u32(sm);
    const int tid  = threadIdx.x;
    const int wid  = tid >> 5;
    const int lane = tid & 31;
    const int qr = lane >> 2, qc = lane & 3;
    const int r8 = lane & 7, g = lane >> 3;

    int blk = blockIdx.x;
    const int hg = blk % 3; blk /= 3;
    const int w = blk & 63; const int b = blk >> 6;
    const int row0 = (w >> 3) * 7, cpix0 = (w & 7) * 7;
    const int col0 = (hg * 4 + wid) * HD;

    // Load q,k,v windows for 4 heads: 2352 16B chunks (49 rows x 4 x 12 tiles)
    for (int it = 0; it < 19; it++) {
        int idx = tid + it * 128;
        if (idx < 2352) {
            int c = idx & 3;
            int r = (idx >> 2) % 49;
            int zt = (idx >> 2) / 49;          // head*3 + tensor
            int hh = zt / 3, tz = zt % 3;
            int pix = (row0 + r / 7) * WW + cpix0 + (r % 7);
            const __half* src = qkvh + ((size_t)(b * NN + pix)) * C3
                              + tz * CC + (hg * 4 + hh) * HD + c * 8;
            cp_async16(sbase + (uint32_t)(zt * ATILE + r * 80 + c * 16), src);
        }
    }
    asm volatile("cp.async.commit_group;");
    cp_wait<0>();
    __syncthreads();

    const uint32_t QB = sbase + (uint32_t)(wid * AHEAD);
    const uint32_t KB = QB + ATILE;
    const uint32_t VB = QB + 2 * ATILE;

    // K fragments (rows clamped to 48; masked cols never used)
    uint32_t Kf[8][2][2];
    #pragma unroll
    for (int up = 0; up < 4; up++)
        #pragma unroll
        for (int s = 0; s < 2; s++) {
            int row = 16 * up + r8 + ((g & 1) << 3);
            if (row > 48) row = 48;
            uint32_t addr = KB + (uint32_t)row * 80u
                          + (uint32_t)(32 * s + ((g >> 1) << 4));
            uint32_t r[4];
            ldm_x4(r, addr);
            Kf[2 * up][s][0] = r[0]; Kf[2 * up][s][1] = r[2];
            Kf[2 * up + 1][s][0] = r[1]; Kf[2 * up + 1][s][1] = r[3];
        }
    // V fragments (trans, rows clamped)
    uint32_t Vf[4][4][2];
    #pragma unroll
    for (int wk = 0; wk < 4; wk++)
        #pragma unroll
        for (int up = 0; up < 2; up++) {
            int row = 16 * wk + r8 + ((g >> 1) << 3);
            if (row > 48) row = 48;
            uint32_t addr = VB + (uint32_t)row * 80u
                          + (uint32_t)(32 * up + ((g & 1) << 4));
            uint32_t r[4];
            ldm_x4_t(r, addr);
            Vf[2 * up][wk][0] = r[0]; Vf[2 * up][wk][1] = r[2];
            Vf[2 * up + 1][wk][0] = r[1]; Vf[2 * up + 1][wk][1] = r[3];
        }

    bool vc0[7], vc1[7];
    #pragma unroll
    for (int u = 0; u < 7; u++) {
        int cb = 8 * u + 2 * qc;
        vc0[u] = cb < WIN;
        vc1[u] = cb + 1 < WIN;
    }

    const float scale = 0.17677669529663687f;

    #pragma unroll
    for (int t = 0; t < 4; t++) {
        uint32_t Qf[2][4];
        #pragma unroll
        for (int s = 0; s < 2; s++) {
            int row = 16 * t + r8 + ((g & 1) << 3);
            if (row > 48) row = 48;
            uint32_t addr = QB + (uint32_t)row * 80u
                          + (uint32_t)(32 * s + ((g >> 1) << 4));
            ldm_x4(Qf[s], addr);
        }
        float S[7][4];
        #pragma unroll
        for (int u = 0; u < 7; u++) {
            S[u][0] = S[u][1] = S[u][2] = S[u][3] = 0.f;
            mma_f16(S[u], Qf[0], Kf[u][0][0], Kf[u][0][1]);
            mma_f16(S[u], Qf[1], Kf[u][1][0], Kf[u][1][1]);
        }

        const int rr0 = 16 * t + qr;
        const int rr1 = rr0 + 8;
        const bool vr0 = rr0 < WIN, vr1 = rr1 < WIN;

        float m0 = -1e30f, m1 = -1e30f;
        #pragma unroll
        for (int u = 0; u < 7; u++) {
            if (vc0[u]) { m0 = fmaxf(m0, S[u][0]); m1 = fmaxf(m1, S[u][2]); }
            if (vc1[u]) { m0 = fmaxf(m0, S[u][1]); m1 = fmaxf(m1, S[u][3]); }
        }
        #pragma unroll
        for (int o = 1; o <= 2; o <<= 1) {
            m0 = fmaxf(m0, __shfl_xor_sync(0xffffffffu, m0, o));
            m1 = fmaxf(m1, __shfl_xor_sync(0xffffffffu, m1, o));
        }

        uint32_t P[8][2];
        P[7][0] = 0u; P[7][1] = 0u;
        float sum0 = 0.f, sum1 = 0.f;
        #pragma unroll
        for (int u = 0; u < 7; u++) {
            float p0 = 0.f, p1 = 0.f, p2 = 0.f, p3 = 0.f;
            if (vr0) {
                if (vc0[u]) p0 = __expf((S[u][0] - m0) * scale);
                if (vc1[u]) p1 = __expf((S[u][1] - m0) * scale);
            }
            if (vr1) {
                if (vc0[u]) p2 = __expf((S[u][2] - m1) * scale);
                if (vc1[u]) p3 = __expf((S[u][3] - m1) * scale);
            }
            sum0 += p0 + p1;
            sum1 += p2 + p3;
            P[u][0] = h2u(__floats2half2_rn(p0, p1));
            P[u][1] = h2u(__floats2half2_rn(p2, p3));
        }
        #pragma unroll
        for (int o = 1; o <= 2; o <<= 1) {
            sum0 += __shfl_xor_sync(0xffffffffu, sum0, o);
            sum1 += __shfl_xor_sync(0xffffffffu, sum1, o);
        }
        const float is0 = vr0 ? 1.f / sum0 : 0.f;
        const float is1 = vr1 ? 1.f / sum1 : 0.f;

        float O[4][4];
        #pragma unroll
        for (int u = 0; u < 4; u++)
            O[u][0] = O[u][1] = O[u][2] = O[u][3] = 0.f;
        #pragma unroll
        for (int wk = 0; wk < 4; wk++) {
            uint32_t afr[4] = { P[2 * wk][0], P[2 * wk][1],
                                P[2 * wk + 1][0], P[2 * wk + 1][1] };
            #pragma unroll
            for (int u = 0; u < 4; u++)
                mma_f16(O[u], afr, Vf[u][wk][0], Vf[u][wk][1]);
        }

        if (vr0) {
            int pix = (row0 + rr0 / 7) * WW + cpix0 + (rr0 % 7);
            __half* base = yh + ((size_t)(b * NN + pix)) * CC + col0;
            #pragma unroll
            for (int u = 0; u < 4; u++)
                *(__half2*)(base + 8 * u + 2 * qc) =
                    __floats2half2_rn(O[u][0] * is0, O[u][1] * is0);
        }
        if (vr1) {
            int pix = (row0 + rr1 / 7) * WW + cpix0 + (rr1 % 7);
            __half* base = yh + ((size_t)(b * NN + pix)) * CC + col0;
            #pragma unroll
            for (int u = 0; u < 4; u++)
                *(__half2*)(base + 8 * u + 2 * qc) =
                    __floats2half2_rn(O[u][2] * is1, O[u][3] * is1);
        }
    }
}

// ---------------------------------------------------------------------------
// Depthwise 3x3 conv on v (fp16) + bias, accumulated into yh (fp16 rmw).
// ---------------------------------------------------------------------------
__global__ __launch_bounds__(256)
void conv_add_h_kernel(const __half* __restrict__ qkvh,
                       const float* __restrict__ w_conv,
                       const float* __restrict__ b_conv,
                       __half* __restrict__ yh)
{
    const int CG = CC / 8;  // 48
    int idx = blockIdx.x * blockDim.x + threadIdx.x;
    if (idx >= BATCH * NN * CG) return;
    int cg = idx % CG;
    int n = (idx / CG) % NN;
    int b = idx / (CG * NN);
    int hh = n / WW, ww = n % WW;
    const int c = cg * 8;

    float acc[8];
    #pragma unroll
    for (int e = 0; e < 8; e++) acc[e] = b_conv[c + e];

    #pragma unroll
    for (int kh = 0; kh < 3; kh++) {
        int hn = hh + kh - 1;
        if ((unsigned)hn >= (unsigned)HH) continue;
        #pragma unroll
        for (int kw = 0; kw < 3; kw++) {
            int wn = ww + kw - 1;
            if ((unsigned)wn >= (unsigned)WW) continue;
            uint4 vr = *(const uint4*)(qkvh + ((size_t)(b * NN + hn * WW + wn)) * C3
                                       + 2 * CC + c);
            const __half2* v2 = (const __half2*)&vr;
            const float* wc = w_conv + (kh * 3 + kw) * CC + c;
            #pragma unroll
            for (int e = 0; e < 4; e++) {
                float2 vf = __half22float2(v2[e]);
                acc[e * 2 + 0] += vf.x * wc[e * 2 + 0];
                acc[e * 2 + 1] += vf.y * wc[e * 2 + 1];
            }
        }
    }

    __half* yo = yh + ((size_t)(b * NN + n)) * CC + c;
    uint4 yv = *(uint4*)yo;
    __half2* y2 = (__half2*)&yv;
    #pragma unroll
    for (int e = 0; e < 4; e++) {
        float2 yf = __half22float2(y2[e]);
        y2[e] = __floats2half2_rn(yf.x + acc[e * 2], yf.y + acc[e * 2 + 1]);
    }
    *(uint4*)yo = yv;
}

// ---------------------------------------------------------------------------
extern "C" void kernel_launch(void* const* d_in, const int* in_sizes, int n_in,
                              void* d_out, int out_size)
{
    const float* x      = (const float*)d_in[0];
    const float* w_qkv  = (const float*)d_in[1];
    const float* w_proj = (const float*)d_in[2];
    const float* b_proj = (const float*)d_in[3];
    const float* w_conv = (const float*)d_in[4];
    const float* b_conv = (const float*)d_in[5];
    float* out = (float*)d_out;

    __half *qkvh_p, *xh_p, *yh_p, *wt1_p, *wt2_p;
    cudaGetSymbolAddress((void**)&qkvh_p, g_qkvh);
    cudaGetSymbolAddress((void**)&xh_p, g_xh);
    cudaGetSymbolAddress((void**)&yh_p, g_yh);
    cudaGetSymbolAddress((void**)&wt1_p, g_wt1);
    cudaGetSymbolAddress((void**)&wt2_p, g_wt2);

    const int gemm_smem = NSTAGE * STAGE_BYTES;  // 81920
    cudaFuncSetAttribute(gemm_f16_kernel<true>,
                         cudaFuncAttributeMaxDynamicSharedMemorySize, gemm_smem);
    cudaFuncSetAttribute(gemm_f16_kernel<false>,
                         cudaFuncAttributeMaxDynamicSharedMemorySize, gemm_smem);
    cudaFuncSetAttribute(attn_tc_kernel,
                         cudaFuncAttributeMaxDynamicSharedMemorySize, ASMEM);

    // 0) fp16 conversions
    {
        int n4 = MROWS * CC / 4;
        to_half_kernel<<<(n4 + 255) / 256, 256>>>(x, xh_p, n4);
        transpose_half_kernel<<<(CC * C3 + 255) / 256, 256>>>(w_qkv, wt1_p, CC, C3);
        transpose_half_kernel<<<(CC * CC + 255) / 256, 256>>>(w_proj, wt2_p, CC, CC);
    }
    // 1) qkvh = x @ w_qkv (fp16 out)
    {
        dim3 grid(C3 / BN, MROWS / BM);
        gemm_f16_kernel<true><<<grid, 256, gemm_smem>>>(xh_p, wt1_p, qkvh_p, nullptr,
                                                        MROWS, C3, CC);
    }
    // 2) tensor-core windowed attention -> yh (fp16)
    attn_tc_kernel<<<BATCH * 64 * 3, 128, ASMEM>>>(qkvh_p, yh_p);
    // 3) yh += depthwise conv3x3(v) + b_conv
    {
        int total = BATCH * NN * (CC / 8);
        conv_add_h_kernel<<<(total + 255) / 256, 256>>>(qkvh_p, w_conv, b_conv, yh_p);
    }
    // 4) out = yh @ w_proj + b_proj (fp32 out)
    {
        dim3 grid(CC / BN, MROWS / BM);
        gemm_f16_kernel<false><<<grid, 256, gemm_smem>>>(yh_p, wt2_p, out, b_proj,
                                                         MROWS, CC, CC);
    }
}

// round 14
// speedup vs baseline: 1.4326x; 1.2552x over previous
#include <cuda_runtime.h>
#include <cuda_fp16.h>
#include <cstdint>

// Problem constants
#define BATCH 16
#define HH 56
#define WW 56
#define NN (HH * WW)          // 3136
#define CC 384
#define C3 (3 * CC)           // 1152
#define NHEADS 12
#define HD 32
#define WSZ 7
#define WIN 49
#define MROWS (BATCH * NN)    // 50176

// GEMM tiling (fp16): 128x128x32 CTA tile, 8 warps of 64x32 (R10 optimum)
#define BM 128
#define BN 128
#define BK 32
#define SROWH 40                  // smem row stride in halves (80B, conflict-free)
#define ABUF (BM * SROWH * 2)     // 10240 bytes per buffer
#define STAGE_BYTES (2 * ABUF)    // 20480
#define NSTAGE 5

// Attention smem: per head Q,K,V tiles of 49 rows x 80B, + conv ring/weights
#define ATILE 3920                // 49 * 80
#define AHEAD (3 * ATILE)         // 11760
#define TILES_BYTES (4 * AHEAD)   // 47040
#define RING_OFF  TILES_BYTES               // 32 ring pixels * 4 heads * 64B = 8192
#define WTS_OFF   (RING_OFF + 8192)         // 9k * 32ch * 4B * 4 heads = 4608
#define BCS_OFF   (WTS_OFF + 4608)          // 4 heads * 32ch * 4B = 512
#define ASMEM     (BCS_OFF + 512)           // 60352

// Scratch (allocation-free rule: __device__ globals)
__device__ __half g_qkvh[(size_t)MROWS * C3];   // 115.5 MB
__device__ __half g_xh[(size_t)MROWS * CC];     // 38.5 MB
__device__ __half g_yh[(size_t)MROWS * CC];     // 38.5 MB
__device__ __half g_wt1[(size_t)C3 * CC];       // w_qkv^T fp16
__device__ __half g_wt2[(size_t)CC * CC];       // w_proj^T fp16

// ---------------------------------------------------------------------------
__device__ __forceinline__ uint32_t smem_u32(const void* p) {
    uint32_t a;
    asm("{ .reg .u64 t; cvta.to.shared.u64 t, %1; cvt.u32.u64 %0, t; }" : "=r"(a) : "l"(p));
    return a;
}
__device__ __forceinline__ void cp_async16(uint32_t saddr, const void* gaddr) {
    asm volatile("cp.async.cg.shared.global [%0], [%1], 16;" :: "r"(saddr), "l"(gaddr));
}
template <int N>
__device__ __forceinline__ void cp_wait() {
    asm volatile("cp.async.wait_group %0;" :: "n"(N) : "memory");
}
__device__ __forceinline__ void mma_f16(float c[4], const uint32_t a[4],
                                        uint32_t b0, uint32_t b1) {
    asm volatile(
        "mma.sync.aligned.m16n8k16.row.col.f32.f16.f16.f32 "
        "{%0,%1,%2,%3}, {%4,%5,%6,%7}, {%8,%9}, {%0,%1,%2,%3};"
        : "+f"(c[0]), "+f"(c[1]), "+f"(c[2]), "+f"(c[3])
        : "r"(a[0]), "r"(a[1]), "r"(a[2]), "r"(a[3]), "r"(b0), "r"(b1));
}
__device__ __forceinline__ void ldm_x4(uint32_t r[4], uint32_t addr) {
    asm volatile("ldmatrix.sync.aligned.m8n8.x4.shared.b16 {%0,%1,%2,%3}, [%4];"
        : "=r"(r[0]), "=r"(r[1]), "=r"(r[2]), "=r"(r[3]) : "r"(addr));
}
__device__ __forceinline__ void ldm_x4_t(uint32_t r[4], uint32_t addr) {
    asm volatile("ldmatrix.sync.aligned.m8n8.x4.trans.shared.b16 {%0,%1,%2,%3}, [%4];"
        : "=r"(r[0]), "=r"(r[1]), "=r"(r[2]), "=r"(r[3]) : "r"(addr));
}
__device__ __forceinline__ uint32_t h2u(__half2 h) {
    return *reinterpret_cast<uint32_t*>(&h);
}

// ---------------------------------------------------------------------------
// fp16 mma.sync GEMM (R10 optimum + 5-stage pipeline).
// ---------------------------------------------------------------------------
template <bool HALF_OUT>
__global__ __launch_bounds__(256, 2)
void gemm_f16_kernel(const __half* __restrict__ A, const __half* __restrict__ Bt,
                     void* __restrict__ Cout, const float* __restrict__ bias,
                     int M, int N, int K)
{
    extern __shared__ char smem[];
    const uint32_t sbase = smem_u32(smem);

    const int tid  = threadIdx.x;
    const int wid  = tid >> 5;
    const int lane = tid & 31;
    const int wm = (wid & 1) * 64;
    const int wn = (wid >> 1) * 32;
    const int qr = lane >> 2;
    const int qc = lane & 3;

    const int nbase = blockIdx.x * BN;
    const size_t mbase = (size_t)blockIdx.y * BM;

    const int row_ld = tid >> 1;
    const int c2_ld  = (tid & 1) << 1;

    const int r8  = lane & 7;
    const int sel = lane >> 3;
    const uint32_t rowadd = (uint32_t)((sel & 1) << 3);
    const uint32_t kbadd  = (uint32_t)((sel >> 1) << 4);
    uint32_t a_off[4], b_off[2];
    #pragma unroll
    for (int i = 0; i < 4; i++)
        a_off[i] = (uint32_t)(wm + 16 * i + rowadd + r8) * (SROWH * 2) + kbadd;
    #pragma unroll
    for (int p = 0; p < 2; p++)
        b_off[p] = (uint32_t)ABUF
                 + (uint32_t)(wn + 16 * p + rowadd + r8) * (SROWH * 2) + kbadd;

    float acc[4][4][4];
    #pragma unroll
    for (int i = 0; i < 4; i++)
        #pragma unroll
        for (int j = 0; j < 4; j++)
            #pragma unroll
            for (int t = 0; t < 4; t++) acc[i][j][t] = 0.f;

    const int nstages = K / BK;

    auto load_stage = [&](int s) {
        const uint32_t base = sbase + (uint32_t)(s % NSTAGE) * STAGE_BYTES;
        const int k0 = s * BK;
        const __half* Ag = A + (mbase + row_ld) * (size_t)K + k0;
        const __half* Bg = Bt + (size_t)(nbase + row_ld) * K + k0;
        const uint32_t soff = (uint32_t)row_ld * (SROWH * 2);
        #pragma unroll
        for (int cc = 0; cc < 2; cc++) {
            const int ch = c2_ld + cc;
            cp_async16(base + soff + ((uint32_t)ch << 4), Ag + (ch << 3));
            cp_async16(base + ABUF + soff + ((uint32_t)ch << 4), Bg + (ch << 3));
        }
        asm volatile("cp.async.commit_group;");
    };

    load_stage(0);
    load_stage(1);
    load_stage(2);
    load_stage(3);

    for (int s = 0; s < nstages; s++) {
        if      (s + 3 < nstages) cp_wait<3>();
        else if (s + 2 < nstages) cp_wait<2>();
        else if (s + 1 < nstages) cp_wait<1>();
        else                      cp_wait<0>();
        __syncthreads();
        if (s + 4 < nstages) load_stage(s + 4);

        const uint32_t sstage = sbase + (uint32_t)(s % NSTAGE) * STAGE_BYTES;
        #pragma unroll
        for (int ks = 0; ks < 2; ks++) {
            const uint32_t kb = (uint32_t)ks << 5;
            uint32_t afr[4][4];
            uint32_t bfr[2][4];
            #pragma unroll
            for (int i = 0; i < 4; i++) ldm_x4(afr[i], sstage + a_off[i] + kb);
            #pragma unroll
            for (int p = 0; p < 2; p++) ldm_x4(bfr[p], sstage + b_off[p] + kb);
            #pragma unroll
            for (int i = 0; i < 4; i++)
                #pragma unroll
                for (int j = 0; j < 4; j++)
                    mma_f16(acc[i][j], afr[i], bfr[j >> 1][j & 1],
                            bfr[j >> 1][(j & 1) + 2]);
        }
    }

    #pragma unroll
    for (int i = 0; i < 4; i++) {
        const size_t row = mbase + wm + i * 16 + qr;
        #pragma unroll
        for (int j = 0; j < 4; j++) {
            const int col = nbase + wn + j * 8 + 2 * qc;
            if (HALF_OUT) {
                __half* Ch = (__half*)Cout;
                *(__half2*)(Ch + row * (size_t)N + col) =
                    __floats2half2_rn(acc[i][j][0], acc[i][j][1]);
                *(__half2*)(Ch + (row + 8) * (size_t)N + col) =
                    __floats2half2_rn(acc[i][j][2], acc[i][j][3]);
            } else {
                float* Cf = (float*)Cout;
                float2 v0 = make_float2(acc[i][j][0], acc[i][j][1]);
                float2 v1 = make_float2(acc[i][j][2], acc[i][j][3]);
                if (bias) {
                    float2 bb = *(const float2*)(bias + col);
                    v0.x += bb.x; v0.y += bb.y;
                    v1.x += bb.x; v1.y += bb.y;
                }
                *(float2*)(Cf + row * (size_t)N + col) = v0;
                *(float2*)(Cf + (row + 8) * (size_t)N + col) = v1;
            }
        }
    }
}

// ---------------------------------------------------------------------------
__global__ void to_half_kernel(const float* __restrict__ in, __half* __restrict__ out, int n4)
{
    int i = blockIdx.x * blockDim.x + threadIdx.x;
    if (i >= n4) return;
    float4 v = ((const float4*)in)[i];
    ((__half2*)out)[i * 2 + 0] = __floats2half2_rn(v.x, v.y);
    ((__half2*)out)[i * 2 + 1] = __floats2half2_rn(v.z, v.w);
}

__global__ void transpose_half_kernel(const float* __restrict__ in, __half* __restrict__ out,
                                      int K, int N)
{
    int i = blockIdx.x * blockDim.x + threadIdx.x;
    if (i >= K * N) return;
    int n = i % N, k = i / N;
    out[(size_t)n * K + k] = __float2half_rn(in[(size_t)k * N + n]);
}

// ---------------------------------------------------------------------------
// TC windowed attention + fused depthwise 3x3 conv(v) + bias.
// Block = (b, window, headgroup of 4), 128 threads, warp = one head.
// Conv uses the resident V tile for interior neighbors + an 8KB ring halo.
// ---------------------------------------------------------------------------
__global__ __launch_bounds__(128)
void attn_tc_kernel(const __half* __restrict__ qkvh,
                    const float* __restrict__ w_conv,
                    const float* __restrict__ b_conv,
                    __half* __restrict__ yh)
{
    extern __shared__ char sm[];
    const uint32_t sbase = smem_u32(sm);
    const int tid  = threadIdx.x;
    const int wid  = tid >> 5;
    const int lane = tid & 31;
    const int qr = lane >> 2, qc = lane & 3;
    const int r8 = lane & 7, g = lane >> 3;

    int blk = blockIdx.x;
    const int hg = blk % 3; blk /= 3;
    const int w = blk & 63; const int b = blk >> 6;
    const int row0 = (w >> 3) * 7, cpix0 = (w & 7) * 7;
    const int col0 = (hg * 4 + wid) * HD;

    // Main q,k,v tiles: 2352 16B chunks
    for (int it = 0; it < 19; it++) {
        int idx = tid + it * 128;
        if (idx < 2352) {
            int c = idx & 3;
            int r = (idx >> 2) % 49;
            int zt = (idx >> 2) / 49;
            int hh = zt / 3, tz = zt % 3;
            int pix = (row0 + r / 7) * WW + cpix0 + (r % 7);
            const __half* src = qkvh + ((size_t)(b * NN + pix)) * C3
                              + tz * CC + (hg * 4 + hh) * HD + c * 8;
            cp_async16(sbase + (uint32_t)(zt * ATILE + r * 80 + c * 16), src);
        }
    }
    // Conv ring halo: 32 ring pixels x 4 heads x 4 chunks = 512 chunks
    for (int it = 0; it < 4; it++) {
        int chunk = tid + it * 128;
        int c4 = chunk & 3;
        int head = (chunk >> 2) & 3;
        int ridx = chunk >> 4;               // 0..31
        int gr, gc;
        if (ridx < 9)       { gr = 0; gc = ridx; }
        else if (ridx < 18) { gr = 8; gc = ridx - 9; }
        else { int e = ridx - 18; gr = 1 + (e >> 1); gc = (e & 1) ? 8 : 0; }
        int r = row0 - 1 + gr, c = cpix0 - 1 + gc;
        uint32_t dst = sbase + (uint32_t)(RING_OFF + ridx * 256 + head * 64 + c4 * 16);
        if ((unsigned)r < (unsigned)HH && (unsigned)c < (unsigned)WW) {
            cp_async16(dst, qkvh + ((size_t)(b * NN + r * WW + c)) * C3
                             + 2 * CC + (hg * 4 + head) * HD + c4 * 8);
        } else {
            *(uint4*)(sm + RING_OFF + ridx * 256 + head * 64 + c4 * 16) =
                make_uint4(0, 0, 0, 0);
        }
    }
    // Conv weights (fp32) per head: 1152 floats
    for (int it = 0; it < 9; it++) {
        int t = tid + it * 128;
        int head = t / 288, rem = t % 288;
        int k = rem / 32, ch = rem % 32;
        ((float*)(sm + WTS_OFF))[t] = w_conv[k * CC + (hg * 4 + head) * HD + ch];
    }
    // Bias per head: 128 floats
    ((float*)(sm + BCS_OFF))[tid] = b_conv[(hg * 4 + (tid >> 5)) * HD + (tid & 31)];

    asm volatile("cp.async.commit_group;");
    cp_wait<0>();
    __syncthreads();

    const uint32_t QB = sbase + (uint32_t)(wid * AHEAD);
    const uint32_t KB = QB + ATILE;
    const uint32_t VB = QB + 2 * ATILE;
    const char* vtile = sm + wid * AHEAD + 2 * ATILE;
    const char* ring  = sm + RING_OFF;
    const float* wts  = (const float*)(sm + WTS_OFF) + wid * 288;
    const float* bcs  = (const float*)(sm + BCS_OFF) + wid * 32;

    // K fragments (rows clamped to 48; masked cols never used)
    uint32_t Kf[8][2][2];
    #pragma unroll
    for (int up = 0; up < 4; up++)
        #pragma unroll
        for (int s = 0; s < 2; s++) {
            int row = 16 * up + r8 + ((g & 1) << 3);
            if (row > 48) row = 48;
            uint32_t addr = KB + (uint32_t)row * 80u
                          + (uint32_t)(32 * s + ((g >> 1) << 4));
            uint32_t r[4];
            ldm_x4(r, addr);
            Kf[2 * up][s][0] = r[0]; Kf[2 * up][s][1] = r[2];
            Kf[2 * up + 1][s][0] = r[1]; Kf[2 * up + 1][s][1] = r[3];
        }
    // V fragments (trans, rows clamped)
    uint32_t Vf[4][4][2];
    #pragma unroll
    for (int wk = 0; wk < 4; wk++)
        #pragma unroll
        for (int up = 0; up < 2; up++) {
            int row = 16 * wk + r8 + ((g >> 1) << 3);
            if (row > 48) row = 48;
            uint32_t addr = VB + (uint32_t)row * 80u
                          + (uint32_t)(32 * up + ((g & 1) << 4));
            uint32_t r[4];
            ldm_x4_t(r, addr);
            Vf[2 * up][wk][0] = r[0]; Vf[2 * up][wk][1] = r[2];
            Vf[2 * up + 1][wk][0] = r[1]; Vf[2 * up + 1][wk][1] = r[3];
        }

    bool vc0[7], vc1[7];
    #pragma unroll
    for (int u = 0; u < 7; u++) {
        int cb = 8 * u + 2 * qc;
        vc0[u] = cb < WIN;
        vc1[u] = cb + 1 < WIN;
    }

    const float scale = 0.17677669529663687f;

    // per-row conv: compute cv[u][2] for a window pixel (wr, wc)
    auto conv_row = [&](int wr, int wc, float cv[4][2]) {
        #pragma unroll
        for (int u = 0; u < 4; u++) {
            float2 bb = *(const float2*)(bcs + 8 * u + 2 * qc);
            cv[u][0] = bb.x; cv[u][1] = bb.y;
        }
        #pragma unroll
        for (int kh = 0; kh < 3; kh++)
            #pragma unroll
            for (int kw = 0; kw < 3; kw++) {
                const int gr = wr + kh, gc = wc + kw;     // 0..8
                const char* vb;
                if ((unsigned)(gr - 1) < 7u && (unsigned)(gc - 1) < 7u) {
                    vb = vtile + ((gr - 1) * 7 + (gc - 1)) * 80;
                } else {
                    int ridx = (gr == 0) ? gc
                             : (gr == 8) ? 9 + gc
                             : 18 + (gr - 1) * 2 + (gc == 8 ? 1 : 0);
                    vb = ring + ridx * 256 + wid * 64;
                }
                const float* wk = wts + (kh * 3 + kw) * 32;
                #pragma unroll
                for (int u = 0; u < 4; u++) {
                    float2 vf = __half22float2(*(const __half2*)(vb + u * 16 + qc * 4));
                    float2 wf = *(const float2*)(wk + 8 * u + 2 * qc);
                    cv[u][0] += vf.x * wf.x;
                    cv[u][1] += vf.y * wf.y;
                }
            }
    };

    #pragma unroll
    for (int t = 0; t < 4; t++) {
        uint32_t Qf[2][4];
        #pragma unroll
        for (int s = 0; s < 2; s++) {
            int row = 16 * t + r8 + ((g & 1) << 3);
            if (row > 48) row = 48;
            uint32_t addr = QB + (uint32_t)row * 80u
                          + (uint32_t)(32 * s + ((g >> 1) << 4));
            ldm_x4(Qf[s], addr);
        }
        float S[7][4];
        #pragma unroll
        for (int u = 0; u < 7; u++) {
            S[u][0] = S[u][1] = S[u][2] = S[u][3] = 0.f;
            mma_f16(S[u], Qf[0], Kf[u][0][0], Kf[u][0][1]);
            mma_f16(S[u], Qf[1], Kf[u][1][0], Kf[u][1][1]);
        }

        const int rr0 = 16 * t + qr;
        const int rr1 = rr0 + 8;
        const bool vr0 = rr0 < WIN, vr1 = rr1 < WIN;

        float m0 = -1e30f, m1 = -1e30f;
        #pragma unroll
        for (int u = 0; u < 7; u++) {
            if (vc0[u]) { m0 = fmaxf(m0, S[u][0]); m1 = fmaxf(m1, S[u][2]); }
            if (vc1[u]) { m0 = fmaxf(m0, S[u][1]); m1 = fmaxf(m1, S[u][3]); }
        }
        #pragma unroll
        for (int o = 1; o <= 2; o <<= 1) {
            m0 = fmaxf(m0, __shfl_xor_sync(0xffffffffu, m0, o));
            m1 = fmaxf(m1, __shfl_xor_sync(0xffffffffu, m1, o));
        }

        uint32_t P[8][2];
        P[7][0] = 0u; P[7][1] = 0u;
        float sum0 = 0.f, sum1 = 0.f;
        #pragma unroll
        for (int u = 0; u < 7; u++) {
            float p0 = 0.f, p1 = 0.f, p2 = 0.f, p3 = 0.f;
            if (vr0) {
                if (vc0[u]) p0 = __expf((S[u][0] - m0) * scale);
                if (vc1[u]) p1 = __expf((S[u][1] - m0) * scale);
            }
            if (vr1) {
                if (vc0[u]) p2 = __expf((S[u][2] - m1) * scale);
                if (vc1[u]) p3 = __expf((S[u][3] - m1) * scale);
            }
            sum0 += p0 + p1;
            sum1 += p2 + p3;
            P[u][0] = h2u(__floats2half2_rn(p0, p1));
            P[u][1] = h2u(__floats2half2_rn(p2, p3));
        }
        #pragma unroll
        for (int o = 1; o <= 2; o <<= 1) {
            sum0 += __shfl_xor_sync(0xffffffffu, sum0, o);
            sum1 += __shfl_xor_sync(0xffffffffu, sum1, o);
        }
        const float is0 = vr0 ? 1.f / sum0 : 0.f;
        const float is1 = vr1 ? 1.f / sum1 : 0.f;

        float O[4][4];
        #pragma unroll
        for (int u = 0; u < 4; u++)
            O[u][0] = O[u][1] = O[u][2] = O[u][3] = 0.f;
        #pragma unroll
        for (int wk = 0; wk < 4; wk++) {
            uint32_t afr[4] = { P[2 * wk][0], P[2 * wk][1],
                                P[2 * wk + 1][0], P[2 * wk + 1][1] };
            #pragma unroll
            for (int u = 0; u < 4; u++)
                mma_f16(O[u], afr, Vf[u][wk][0], Vf[u][wk][1]);
        }

        if (vr0) {
            const int wr = rr0 / 7, wc = rr0 % 7;
            float cv[4][2];
            conv_row(wr, wc, cv);
            int pix = (row0 + wr) * WW + cpix0 + wc;
            __half* base = yh + ((size_t)(b * NN + pix)) * CC + col0;
            #pragma unroll
            for (int u = 0; u < 4; u++)
                *(__half2*)(base + 8 * u + 2 * qc) =
                    __floats2half2_rn(O[u][0] * is0 + cv[u][0],
                                      O[u][1] * is0 + cv[u][1]);
        }
        if (vr1) {
            const int wr = rr1 / 7, wc = rr1 % 7;
            float cv[4][2];
            conv_row(wr, wc, cv);
            int pix = (row0 + wr) * WW + cpix0 + wc;
            __half* base = yh + ((size_t)(b * NN + pix)) * CC + col0;
            #pragma unroll
            for (int u = 0; u < 4; u++)
                *(__half2*)(base + 8 * u + 2 * qc) =
                    __floats2half2_rn(O[u][2] * is1 + cv[u][0],
                                      O[u][3] * is1 + cv[u][1]);
        }
    }
}

// ---------------------------------------------------------------------------
extern "C" void kernel_launch(void* const* d_in, const int* in_sizes, int n_in,
                              void* d_out, int out_size)
{
    const float* x      = (const float*)d_in[0];
    const float* w_qkv  = (const float*)d_in[1];
    const float* w_proj = (const float*)d_in[2];
    const float* b_proj = (const float*)d_in[3];
    const float* w_conv = (const float*)d_in[4];
    const float* b_conv = (const float*)d_in[5];
    float* out = (float*)d_out;

    __half *qkvh_p, *xh_p, *yh_p, *wt1_p, *wt2_p;
    cudaGetSymbolAddress((void**)&qkvh_p, g_qkvh);
    cudaGetSymbolAddress((void**)&xh_p, g_xh);
    cudaGetSymbolAddress((void**)&yh_p, g_yh);
    cudaGetSymbolAddress((void**)&wt1_p, g_wt1);
    cudaGetSymbolAddress((void**)&wt2_p, g_wt2);

    const int gemm_smem = NSTAGE * STAGE_BYTES;  // 102400
    cudaFuncSetAttribute(gemm_f16_kernel<true>,
                         cudaFuncAttributeMaxDynamicSharedMemorySize, gemm_smem);
    cudaFuncSetAttribute(gemm_f16_kernel<false>,
                         cudaFuncAttributeMaxDynamicSharedMemorySize, gemm_smem);
    cudaFuncSetAttribute(attn_tc_kernel,
                         cudaFuncAttributeMaxDynamicSharedMemorySize, ASMEM);

    // 0) fp16 conversions
    {
        int n4 = MROWS * CC / 4;
        to_half_kernel<<<(n4 + 255) / 256, 256>>>(x, xh_p, n4);
        transpose_half_kernel<<<(CC * C3 + 255) / 256, 256>>>(w_qkv, wt1_p, CC, C3);
        transpose_half_kernel<<<(CC * CC + 255) / 256, 256>>>(w_proj, wt2_p, CC, CC);
    }
    // 1) qkvh = x @ w_qkv (fp16 out)
    {
        dim3 grid(C3 / BN, MROWS / BM);
        gemm_f16_kernel<true><<<grid, 256, gemm_smem>>>(xh_p, wt1_p, qkvh_p, nullptr,
                                                        MROWS, C3, CC);
    }
    // 2) TC windowed attention + fused depthwise conv -> yh (fp16)
    attn_tc_kernel<<<BATCH * 64 * 3, 128, ASMEM>>>(qkvh_p, w_conv, b_conv, yh_p);
    // 3) out = yh @ w_proj + b_proj (fp32 out)
    {
        dim3 grid(CC / BN, MROWS / BM);
        gemm_f16_kernel<false><<<grid, 256, gemm_smem>>>(yh_p, wt2_p, out, b_proj,
                                                         MROWS, CC, CC);
    }
}

// round 15
// speedup vs baseline: 1.5517x; 1.0831x over previous
#include <cuda_runtime.h>
#include <cuda_fp16.h>
#include <cstdint>

// Problem constants
#define BATCH 16
#define HH 56
#define WW 56
#define NN (HH * WW)          // 3136
#define CC 384
#define C3 (3 * CC)           // 1152
#define NHEADS 12
#define HD 32
#define WSZ 7
#define WIN 49
#define MROWS (BATCH * NN)    // 50176

// GEMM tiling (fp16): 128x128x32 CTA tile, 16 warps of 32x32, 512 threads
#define BM 128
#define BN 128
#define BK 32
#define SROWH 40                  // smem row stride in halves (80B, conflict-free)
#define ABUF (BM * SROWH * 2)     // 10240 bytes per buffer
#define STAGE_BYTES (2 * ABUF)    // 20480
#define NSTAGE 5

// Attention smem: per head Q,K,V tiles of 49 rows x 80B, + conv ring/weights
#define ATILE 3920                // 49 * 80
#define AHEAD (3 * ATILE)         // 11760
#define TILES_BYTES (4 * AHEAD)   // 47040
#define RING_OFF  TILES_BYTES               // 32 ring pixels * 4 heads * 64B = 8192
#define WTS_OFF   (RING_OFF + 8192)         // 9k * 32ch * 4B * 4 heads = 4608
#define BCS_OFF   (WTS_OFF + 4608)          // 4 heads * 32ch * 4B = 512
#define ASMEM     (BCS_OFF + 512)           // 60352

// Scratch (allocation-free rule: __device__ globals)
__device__ __half g_qkvh[(size_t)MROWS * C3];   // 115.5 MB
__device__ __half g_xh[(size_t)MROWS * CC];     // 38.5 MB
__device__ __half g_yh[(size_t)MROWS * CC];     // 38.5 MB
__device__ __half g_wt1[(size_t)C3 * CC];       // w_qkv^T fp16
__device__ __half g_wt2[(size_t)CC * CC];       // w_proj^T fp16

// ---------------------------------------------------------------------------
__device__ __forceinline__ uint32_t smem_u32(const void* p) {
    uint32_t a;
    asm("{ .reg .u64 t; cvta.to.shared.u64 t, %1; cvt.u32.u64 %0, t; }" : "=r"(a) : "l"(p));
    return a;
}
__device__ __forceinline__ void cp_async16(uint32_t saddr, const void* gaddr) {
    asm volatile("cp.async.cg.shared.global [%0], [%1], 16;" :: "r"(saddr), "l"(gaddr));
}
template <int N>
__device__ __forceinline__ void cp_wait() {
    asm volatile("cp.async.wait_group %0;" :: "n"(N) : "memory");
}
__device__ __forceinline__ void mma_f16(float c[4], const uint32_t a[4],
                                        uint32_t b0, uint32_t b1) {
    asm volatile(
        "mma.sync.aligned.m16n8k16.row.col.f32.f16.f16.f32 "
        "{%0,%1,%2,%3}, {%4,%5,%6,%7}, {%8,%9}, {%0,%1,%2,%3};"
        : "+f"(c[0]), "+f"(c[1]), "+f"(c[2]), "+f"(c[3])
        : "r"(a[0]), "r"(a[1]), "r"(a[2]), "r"(a[3]), "r"(b0), "r"(b1));
}
__device__ __forceinline__ void ldm_x4(uint32_t r[4], uint32_t addr) {
    asm volatile("ldmatrix.sync.aligned.m8n8.x4.shared.b16 {%0,%1,%2,%3}, [%4];"
        : "=r"(r[0]), "=r"(r[1]), "=r"(r[2]), "=r"(r[3]) : "r"(addr));
}
__device__ __forceinline__ void ldm_x4_t(uint32_t r[4], uint32_t addr) {
    asm volatile("ldmatrix.sync.aligned.m8n8.x4.trans.shared.b16 {%0,%1,%2,%3}, [%4];"
        : "=r"(r[0]), "=r"(r[1]), "=r"(r[2]), "=r"(r[3]) : "r"(addr));
}
__device__ __forceinline__ uint32_t h2u(__half2 h) {
    return *reinterpret_cast<uint32_t*>(&h);
}

// ---------------------------------------------------------------------------
// fp16 mma.sync GEMM: 512 threads, 16 warps (4m x 4n), 32x32 per warp.
// 128x128x32 CTA tile, 5-stage cp.async pipeline. Targets 2 CTA/SM (48% occ).
// ---------------------------------------------------------------------------
template <bool HALF_OUT>
__global__ __launch_bounds__(512, 2)
void gemm_f16_kernel(const __half* __restrict__ A, const __half* __restrict__ Bt,
                     void* __restrict__ Cout, const float* __restrict__ bias,
                     int M, int N, int K)
{
    extern __shared__ char smem[];
    const uint32_t sbase = smem_u32(smem);

    const int tid  = threadIdx.x;
    const int wid  = tid >> 5;
    const int lane = tid & 31;
    const int wm = (wid & 3) * 32;     // warp m offset (0..96)
    const int wn = (wid >> 2) * 32;    // warp n offset (0..96)
    const int qr = lane >> 2;
    const int qc = lane & 3;

    const int nbase = blockIdx.x * BN;
    const size_t mbase = (size_t)blockIdx.y * BM;

    // loader: 4 threads per row, 1 chunk A + 1 chunk B each
    const int row_ld = tid >> 2;       // 0..127
    const int ch_ld  = tid & 3;        // 16B chunk 0..3

    const int r8  = lane & 7;
    const int sel = lane >> 3;
    const uint32_t rowadd = (uint32_t)((sel & 1) << 3);
    const uint32_t kbadd  = (uint32_t)((sel >> 1) << 4);
    uint32_t a_off[2], b_off[2];
    #pragma unroll
    for (int i = 0; i < 2; i++)
        a_off[i] = (uint32_t)(wm + 16 * i + rowadd + r8) * (SROWH * 2) + kbadd;
    #pragma unroll
    for (int p = 0; p < 2; p++)
        b_off[p] = (uint32_t)ABUF
                 + (uint32_t)(wn + 16 * p + rowadd + r8) * (SROWH * 2) + kbadd;

    float acc[2][4][4];
    #pragma unroll
    for (int i = 0; i < 2; i++)
        #pragma unroll
        for (int j = 0; j < 4; j++)
            #pragma unroll
            for (int t = 0; t < 4; t++) acc[i][j][t] = 0.f;

    const int nstages = K / BK;

    auto load_stage = [&](int s) {
        const uint32_t base = sbase + (uint32_t)(s % NSTAGE) * STAGE_BYTES;
        const int k0 = s * BK;
        const __half* Ag = A + (mbase + row_ld) * (size_t)K + k0;
        const __half* Bg = Bt + (size_t)(nbase + row_ld) * K + k0;
        const uint32_t soff = (uint32_t)row_ld * (SROWH * 2) + ((uint32_t)ch_ld << 4);
        cp_async16(base + soff, Ag + (ch_ld << 3));
        cp_async16(base + ABUF + soff, Bg + (ch_ld << 3));
        asm volatile("cp.async.commit_group;");
    };

    load_stage(0);
    load_stage(1);
    load_stage(2);
    load_stage(3);

    for (int s = 0; s < nstages; s++) {
        if      (s + 3 < nstages) cp_wait<3>();
        else if (s + 2 < nstages) cp_wait<2>();
        else if (s + 1 < nstages) cp_wait<1>();
        else                      cp_wait<0>();
        __syncthreads();
        if (s + 4 < nstages) load_stage(s + 4);

        const uint32_t sstage = sbase + (uint32_t)(s % NSTAGE) * STAGE_BYTES;
        #pragma unroll
        for (int ks = 0; ks < 2; ks++) {
            const uint32_t kb = (uint32_t)ks << 5;
            uint32_t afr[2][4];
            uint32_t bfr[2][4];
            #pragma unroll
            for (int i = 0; i < 2; i++) ldm_x4(afr[i], sstage + a_off[i] + kb);
            #pragma unroll
            for (int p = 0; p < 2; p++) ldm_x4(bfr[p], sstage + b_off[p] + kb);
            #pragma unroll
            for (int i = 0; i < 2; i++)
                #pragma unroll
                for (int j = 0; j < 4; j++)
                    mma_f16(acc[i][j], afr[i], bfr[j >> 1][j & 1],
                            bfr[j >> 1][(j & 1) + 2]);
        }
    }

    #pragma unroll
    for (int i = 0; i < 2; i++) {
        const size_t row = mbase + wm + i * 16 + qr;
        #pragma unroll
        for (int j = 0; j < 4; j++) {
            const int col = nbase + wn + j * 8 + 2 * qc;
            if (HALF_OUT) {
                __half* Ch = (__half*)Cout;
                *(__half2*)(Ch + row * (size_t)N + col) =
                    __floats2half2_rn(acc[i][j][0], acc[i][j][1]);
                *(__half2*)(Ch + (row + 8) * (size_t)N + col) =
                    __floats2half2_rn(acc[i][j][2], acc[i][j][3]);
            } else {
                float* Cf = (float*)Cout;
                float2 v0 = make_float2(acc[i][j][0], acc[i][j][1]);
                float2 v1 = make_float2(acc[i][j][2], acc[i][j][3]);
                if (bias) {
                    float2 bb = *(const float2*)(bias + col);
                    v0.x += bb.x; v0.y += bb.y;
                    v1.x += bb.x; v1.y += bb.y;
                }
                *(float2*)(Cf + row * (size_t)N + col) = v0;
                *(float2*)(Cf + (row + 8) * (size_t)N + col) = v1;
            }
        }
    }
}

// ---------------------------------------------------------------------------
__global__ void to_half_kernel(const float* __restrict__ in, __half* __restrict__ out, int n4)
{
    int i = blockIdx.x * blockDim.x + threadIdx.x;
    if (i >= n4) return;
    float4 v = ((const float4*)in)[i];
    ((__half2*)out)[i * 2 + 0] = __floats2half2_rn(v.x, v.y);
    ((__half2*)out)[i * 2 + 1] = __floats2half2_rn(v.z, v.w);
}

__global__ void transpose_half_kernel(const float* __restrict__ in, __half* __restrict__ out,
                                      int K, int N)
{
    int i = blockIdx.x * blockDim.x + threadIdx.x;
    if (i >= K * N) return;
    int n = i % N, k = i / N;
    out[(size_t)n * K + k] = __float2half_rn(in[(size_t)k * N + n]);
}

// ---------------------------------------------------------------------------
// TC windowed attention + fused depthwise 3x3 conv(v) + bias (R14, unchanged).
// ---------------------------------------------------------------------------
__global__ __launch_bounds__(128)
void attn_tc_kernel(const __half* __restrict__ qkvh,
                    const float* __restrict__ w_conv,
                    const float* __restrict__ b_conv,
                    __half* __restrict__ yh)
{
    extern __shared__ char sm[];
    const uint32_t sbase = smem_u32(sm);
    const int tid  = threadIdx.x;
    const int wid  = tid >> 5;
    const int lane = tid & 31;
    const int qr = lane >> 2, qc = lane & 3;
    const int r8 = lane & 7, g = lane >> 3;

    int blk = blockIdx.x;
    const int hg = blk % 3; blk /= 3;
    const int w = blk & 63; const int b = blk >> 6;
    const int row0 = (w >> 3) * 7, cpix0 = (w & 7) * 7;
    const int col0 = (hg * 4 + wid) * HD;

    // Main q,k,v tiles: 2352 16B chunks
    for (int it = 0; it < 19; it++) {
        int idx = tid + it * 128;
        if (idx < 2352) {
            int c = idx & 3;
            int r = (idx >> 2) % 49;
            int zt = (idx >> 2) / 49;
            int hh = zt / 3, tz = zt % 3;
            int pix = (row0 + r / 7) * WW + cpix0 + (r % 7);
            const __half* src = qkvh + ((size_t)(b * NN + pix)) * C3
                              + tz * CC + (hg * 4 + hh) * HD + c * 8;
            cp_async16(sbase + (uint32_t)(zt * ATILE + r * 80 + c * 16), src);
        }
    }
    // Conv ring halo: 32 ring pixels x 4 heads x 4 chunks = 512 chunks
    for (int it = 0; it < 4; it++) {
        int chunk = tid + it * 128;
        int c4 = chunk & 3;
        int head = (chunk >> 2) & 3;
        int ridx = chunk >> 4;               // 0..31
        int gr, gc;
        if (ridx < 9)       { gr = 0; gc = ridx; }
        else if (ridx < 18) { gr = 8; gc = ridx - 9; }
        else { int e = ridx - 18; gr = 1 + (e >> 1); gc = (e & 1) ? 8 : 0; }
        int r = row0 - 1 + gr, c = cpix0 - 1 + gc;
        uint32_t dst = sbase + (uint32_t)(RING_OFF + ridx * 256 + head * 64 + c4 * 16);
        if ((unsigned)r < (unsigned)HH && (unsigned)c < (unsigned)WW) {
            cp_async16(dst, qkvh + ((size_t)(b * NN + r * WW + c)) * C3
                             + 2 * CC + (hg * 4 + head) * HD + c4 * 8);
        } else {
            *(uint4*)(sm + RING_OFF + ridx * 256 + head * 64 + c4 * 16) =
                make_uint4(0, 0, 0, 0);
        }
    }
    // Conv weights (fp32) per head: 1152 floats
    for (int it = 0; it < 9; it++) {
        int t = tid + it * 128;
        int head = t / 288, rem = t % 288;
        int k = rem / 32, ch = rem % 32;
        ((float*)(sm + WTS_OFF))[t] = w_conv[k * CC + (hg * 4 + head) * HD + ch];
    }
    // Bias per head: 128 floats
    ((float*)(sm + BCS_OFF))[tid] = b_conv[(hg * 4 + (tid >> 5)) * HD + (tid & 31)];

    asm volatile("cp.async.commit_group;");
    cp_wait<0>();
    __syncthreads();

    const uint32_t QB = sbase + (uint32_t)(wid * AHEAD);
    const uint32_t KB = QB + ATILE;
    const uint32_t VB = QB + 2 * ATILE;
    const char* vtile = sm + wid * AHEAD + 2 * ATILE;
    const char* ring  = sm + RING_OFF;
    const float* wts  = (const float*)(sm + WTS_OFF) + wid * 288;
    const float* bcs  = (const float*)(sm + BCS_OFF) + wid * 32;

    // K fragments (rows clamped to 48; masked cols never used)
    uint32_t Kf[8][2][2];
    #pragma unroll
    for (int up = 0; up < 4; up++)
        #pragma unroll
        for (int s = 0; s < 2; s++) {
            int row = 16 * up + r8 + ((g & 1) << 3);
            if (row > 48) row = 48;
            uint32_t addr = KB + (uint32_t)row * 80u
                          + (uint32_t)(32 * s + ((g >> 1) << 4));
            uint32_t r[4];
            ldm_x4(r, addr);
            Kf[2 * up][s][0] = r[0]; Kf[2 * up][s][1] = r[2];
            Kf[2 * up + 1][s][0] = r[1]; Kf[2 * up + 1][s][1] = r[3];
        }
    // V fragments (trans, rows clamped)
    uint32_t Vf[4][4][2];
    #pragma unroll
    for (int wk = 0; wk < 4; wk++)
        #pragma unroll
        for (int up = 0; up < 2; up++) {
            int row = 16 * wk + r8 + ((g >> 1) << 3);
            if (row > 48) row = 48;
            uint32_t addr = VB + (uint32_t)row * 80u
                          + (uint32_t)(32 * up + ((g & 1) << 4));
            uint32_t r[4];
            ldm_x4_t(r, addr);
            Vf[2 * up][wk][0] = r[0]; Vf[2 * up][wk][1] = r[2];
            Vf[2 * up + 1][wk][0] = r[1]; Vf[2 * up + 1][wk][1] = r[3];
        }

    bool vc0[7], vc1[7];
    #pragma unroll
    for (int u = 0; u < 7; u++) {
        int cb = 8 * u + 2 * qc;
        vc0[u] = cb < WIN;
        vc1[u] = cb + 1 < WIN;
    }

    const float scale = 0.17677669529663687f;

    auto conv_row = [&](int wr, int wc, float cv[4][2]) {
        #pragma unroll
        for (int u = 0; u < 4; u++) {
            float2 bb = *(const float2*)(bcs + 8 * u + 2 * qc);
            cv[u][0] = bb.x; cv[u][1] = bb.y;
        }
        #pragma unroll
        for (int kh = 0; kh < 3; kh++)
            #pragma unroll
            for (int kw = 0; kw < 3; kw++) {
                const int gr = wr + kh, gc = wc + kw;     // 0..8
                const char* vb;
                if ((unsigned)(gr - 1) < 7u && (unsigned)(gc - 1) < 7u) {
                    vb = vtile + ((gr - 1) * 7 + (gc - 1)) * 80;
                } else {
                    int ridx = (gr == 0) ? gc
                             : (gr == 8) ? 9 + gc
                             : 18 + (gr - 1) * 2 + (gc == 8 ? 1 : 0);
                    vb = ring + ridx * 256 + wid * 64;
                }
                const float* wk = wts + (kh * 3 + kw) * 32;
                #pragma unroll
                for (int u = 0; u < 4; u++) {
                    float2 vf = __half22float2(*(const __half2*)(vb + u * 16 + qc * 4));
                    float2 wf = *(const float2*)(wk + 8 * u + 2 * qc);
                    cv[u][0] += vf.x * wf.x;
                    cv[u][1] += vf.y * wf.y;
                }
            }
    };

    #pragma unroll
    for (int t = 0; t < 4; t++) {
        uint32_t Qf[2][4];
        #pragma unroll
        for (int s = 0; s < 2; s++) {
            int row = 16 * t + r8 + ((g & 1) << 3);
            if (row > 48) row = 48;
            uint32_t addr = QB + (uint32_t)row * 80u
                          + (uint32_t)(32 * s + ((g >> 1) << 4));
            ldm_x4(Qf[s], addr);
        }
        float S[7][4];
        #pragma unroll
        for (int u = 0; u < 7; u++) {
            S[u][0] = S[u][1] = S[u][2] = S[u][3] = 0.f;
            mma_f16(S[u], Qf[0], Kf[u][0][0], Kf[u][0][1]);
            mma_f16(S[u], Qf[1], Kf[u][1][0], Kf[u][1][1]);
        }

        const int rr0 = 16 * t + qr;
        const int rr1 = rr0 + 8;
        const bool vr0 = rr0 < WIN, vr1 = rr1 < WIN;

        float m0 = -1e30f, m1 = -1e30f;
        #pragma unroll
        for (int u = 0; u < 7; u++) {
            if (vc0[u]) { m0 = fmaxf(m0, S[u][0]); m1 = fmaxf(m1, S[u][2]); }
            if (vc1[u]) { m0 = fmaxf(m0, S[u][1]); m1 = fmaxf(m1, S[u][3]); }
        }
        #pragma unroll
        for (int o = 1; o <= 2; o <<= 1) {
            m0 = fmaxf(m0, __shfl_xor_sync(0xffffffffu, m0, o));
            m1 = fmaxf(m1, __shfl_xor_sync(0xffffffffu, m1, o));
        }

        uint32_t P[8][2];
        P[7][0] = 0u; P[7][1] = 0u;
        float sum0 = 0.f, sum1 = 0.f;
        #pragma unroll
        for (int u = 0; u < 7; u++) {
            float p0 = 0.f, p1 = 0.f, p2 = 0.f, p3 = 0.f;
            if (vr0) {
                if (vc0[u]) p0 = __expf((S[u][0] - m0) * scale);
                if (vc1[u]) p1 = __expf((S[u][1] - m0) * scale);
            }
            if (vr1) {
                if (vc0[u]) p2 = __expf((S[u][2] - m1) * scale);
                if (vc1[u]) p3 = __expf((S[u][3] - m1) * scale);
            }
            sum0 += p0 + p1;
            sum1 += p2 + p3;
            P[u][0] = h2u(__floats2half2_rn(p0, p1));
            P[u][1] = h2u(__floats2half2_rn(p2, p3));
        }
        #pragma unroll
        for (int o = 1; o <= 2; o <<= 1) {
            sum0 += __shfl_xor_sync(0xffffffffu, sum0, o);
            sum1 += __shfl_xor_sync(0xffffffffu, sum1, o);
        }
        const float is0 = vr0 ? 1.f / sum0 : 0.f;
        const float is1 = vr1 ? 1.f / sum1 : 0.f;

        float O[4][4];
        #pragma unroll
        for (int u = 0; u < 4; u++)
            O[u][0] = O[u][1] = O[u][2] = O[u][3] = 0.f;
        #pragma unroll
        for (int wk = 0; wk < 4; wk++) {
            uint32_t afr[4] = { P[2 * wk][0], P[2 * wk][1],
                                P[2 * wk + 1][0], P[2 * wk + 1][1] };
            #pragma unroll
            for (int u = 0; u < 4; u++)
                mma_f16(O[u], afr, Vf[u][wk][0], Vf[u][wk][1]);
        }

        if (vr0) {
            const int wr = rr0 / 7, wc = rr0 % 7;
            float cv[4][2];
            conv_row(wr, wc, cv);
            int pix = (row0 + wr) * WW + cpix0 + wc;
            __half* base = yh + ((size_t)(b * NN + pix)) * CC + col0;
            #pragma unroll
            for (int u = 0; u < 4; u++)
                *(__half2*)(base + 8 * u + 2 * qc) =
                    __floats2half2_rn(O[u][0] * is0 + cv[u][0],
                                      O[u][1] * is0 + cv[u][1]);
        }
        if (vr1) {
            const int wr = rr1 / 7, wc = rr1 % 7;
            float cv[4][2];
            conv_row(wr, wc, cv);
            int pix = (row0 + wr) * WW + cpix0 + wc;
            __half* base = yh + ((size_t)(b * NN + pix)) * CC + col0;
            #pragma unroll
            for (int u = 0; u < 4; u++)
                *(__half2*)(base + 8 * u + 2 * qc) =
                    __floats2half2_rn(O[u][2] * is1 + cv[u][0],
                                      O[u][3] * is1 + cv[u][1]);
        }
    }
}

// ---------------------------------------------------------------------------
extern "C" void kernel_launch(void* const* d_in, const int* in_sizes, int n_in,
                              void* d_out, int out_size)
{
    const float* x      = (const float*)d_in[0];
    const float* w_qkv  = (const float*)d_in[1];
    const float* w_proj = (const float*)d_in[2];
    const float* b_proj = (const float*)d_in[3];
    const float* w_conv = (const float*)d_in[4];
    const float* b_conv = (const float*)d_in[5];
    float* out = (float*)d_out;

    __half *qkvh_p, *xh_p, *yh_p, *wt1_p, *wt2_p;
    cudaGetSymbolAddress((void**)&qkvh_p, g_qkvh);
    cudaGetSymbolAddress((void**)&xh_p, g_xh);
    cudaGetSymbolAddress((void**)&yh_p, g_yh);
    cudaGetSymbolAddress((void**)&wt1_p, g_wt1);
    cudaGetSymbolAddress((void**)&wt2_p, g_wt2);

    const int gemm_smem = NSTAGE * STAGE_BYTES;  // 102400
    cudaFuncSetAttribute(gemm_f16_kernel<true>,
                         cudaFuncAttributeMaxDynamicSharedMemorySize, gemm_smem);
    cudaFuncSetAttribute(gemm_f16_kernel<false>,
                         cudaFuncAttributeMaxDynamicSharedMemorySize, gemm_smem);
    cudaFuncSetAttribute(attn_tc_kernel,
                         cudaFuncAttributeMaxDynamicSharedMemorySize, ASMEM);

    // 0) fp16 conversions
    {
        int n4 = MROWS * CC / 4;
        to_half_kernel<<<(n4 + 255) / 256, 256>>>(x, xh_p, n4);
        transpose_half_kernel<<<(CC * C3 + 255) / 256, 256>>>(w_qkv, wt1_p, CC, C3);
        transpose_half_kernel<<<(CC * CC + 255) / 256, 256>>>(w_proj, wt2_p, CC, CC);
    }
    // 1) qkvh = x @ w_qkv (fp16 out)
    {
        dim3 grid(C3 / BN, MROWS / BM);
        gemm_f16_kernel<true><<<grid, 512, gemm_smem>>>(xh_p, wt1_p, qkvh_p, nullptr,
                                                        MROWS, C3, CC);
    }
    // 2) TC windowed attention + fused depthwise conv -> yh (fp16)
    attn_tc_kernel<<<BATCH * 64 * 3, 128, ASMEM>>>(qkvh_p, w_conv, b_conv, yh_p);
    // 3) out = yh @ w_proj + b_proj (fp32 out)
    {
        dim3 grid(CC / BN, MROWS / BM);
        gemm_f16_kernel<false><<<grid, 512, gemm_smem>>>(yh_p, wt2_p, out, b_proj,
                                                         MROWS, CC, CC);
    }
}

// round 16
// speedup vs baseline: 1.6382x; 1.0558x over previous
#include <cuda_runtime.h>
#include <cuda_fp16.h>
#include <cstdint>

// Problem constants
#define BATCH 16
#define HH 56
#define WW 56
#define NN (HH * WW)          // 3136
#define CC 384
#define C3 (3 * CC)           // 1152
#define NHEADS 12
#define HD 32
#define WSZ 7
#define WIN 49
#define MROWS (BATCH * NN)    // 50176

// GEMM tiling (fp16): 128x128x32 CTA tile, 16 warps of 32x32, 512 threads.
// K is ALWAYS 384 in this problem -> 12 stages, fully unrolled.
#define BM 128
#define BN 128
#define BK 32
#define KK 384
#define NSTAGES_TOT (KK / BK)     // 12
#define SROWH 40                  // smem row stride in halves (80B, conflict-free)
#define ABUF (BM * SROWH * 2)     // 10240 bytes per buffer
#define STAGE_BYTES (2 * ABUF)    // 20480
#define NSTAGE 5

// Attention smem: per head Q,K,V tiles of 49 rows x 80B, + conv ring/weights
#define ATILE 3920                // 49 * 80
#define AHEAD (3 * ATILE)         // 11760
#define TILES_BYTES (4 * AHEAD)   // 47040
#define RING_OFF  TILES_BYTES               // 32 ring pixels * 4 heads * 64B = 8192
#define WTS_OFF   (RING_OFF + 8192)         // 9k * 32ch * 4B * 4 heads = 4608
#define BCS_OFF   (WTS_OFF + 4608)          // 4 heads * 32ch * 4B = 512
#define ASMEM     (BCS_OFF + 512)           // 60352

// Scratch (allocation-free rule: __device__ globals)
__device__ __half g_qkvh[(size_t)MROWS * C3];   // 115.5 MB
__device__ __half g_xh[(size_t)MROWS * CC];     // 38.5 MB
__device__ __half g_yh[(size_t)MROWS * CC];     // 38.5 MB
__device__ __half g_wt1[(size_t)C3 * CC];       // w_qkv^T fp16
__device__ __half g_wt2[(size_t)CC * CC];       // w_proj^T fp16

// ---------------------------------------------------------------------------
__device__ __forceinline__ uint32_t smem_u32(const void* p) {
    uint32_t a;
    asm("{ .reg .u64 t; cvta.to.shared.u64 t, %1; cvt.u32.u64 %0, t; }" : "=r"(a) : "l"(p));
    return a;
}
__device__ __forceinline__ void cp_async16(uint32_t saddr, const void* gaddr) {
    asm volatile("cp.async.cg.shared.global [%0], [%1], 16;" :: "r"(saddr), "l"(gaddr));
}
template <int N>
__device__ __forceinline__ void cp_wait() {
    asm volatile("cp.async.wait_group %0;" :: "n"(N) : "memory");
}
__device__ __forceinline__ void mma_f16(float c[4], const uint32_t a[4],
                                        uint32_t b0, uint32_t b1) {
    asm volatile(
        "mma.sync.aligned.m16n8k16.row.col.f32.f16.f16.f32 "
        "{%0,%1,%2,%3}, {%4,%5,%6,%7}, {%8,%9}, {%0,%1,%2,%3};"
        : "+f"(c[0]), "+f"(c[1]), "+f"(c[2]), "+f"(c[3])
        : "r"(a[0]), "r"(a[1]), "r"(a[2]), "r"(a[3]), "r"(b0), "r"(b1));
}
__device__ __forceinline__ void ldm_x4(uint32_t r[4], uint32_t addr) {
    asm volatile("ldmatrix.sync.aligned.m8n8.x4.shared.b16 {%0,%1,%2,%3}, [%4];"
        : "=r"(r[0]), "=r"(r[1]), "=r"(r[2]), "=r"(r[3]) : "r"(addr));
}
__device__ __forceinline__ void ldm_x4_t(uint32_t r[4], uint32_t addr) {
    asm volatile("ldmatrix.sync.aligned.m8n8.x4.trans.shared.b16 {%0,%1,%2,%3}, [%4];"
        : "=r"(r[0]), "=r"(r[1]), "=r"(r[2]), "=r"(r[3]) : "r"(addr));
}
__device__ __forceinline__ uint32_t h2u(__half2 h) {
    return *reinterpret_cast<uint32_t*>(&h);
}

// ---------------------------------------------------------------------------
// fp16 mma.sync GEMM, K=384 compile-time: 512 threads, 16 warps (4m x 4n),
// 32x32/warp, 5-buffer cp.async pipeline over 12 fully-unrolled stages.
// ---------------------------------------------------------------------------
template <bool HALF_OUT>
__global__ __launch_bounds__(512, 2)
void gemm_f16_kernel(const __half* __restrict__ A, const __half* __restrict__ Bt,
                     void* __restrict__ Cout, const float* __restrict__ bias,
                     int M, int N)
{
    extern __shared__ char smem[];
    const uint32_t sbase = smem_u32(smem);

    const int tid  = threadIdx.x;
    const int wid  = tid >> 5;
    const int lane = tid & 31;
    const int wm = (wid & 3) * 32;
    const int wn = (wid >> 2) * 32;
    const int qr = lane >> 2;
    const int qc = lane & 3;

    const int nbase = blockIdx.x * BN;
    const size_t mbase = (size_t)blockIdx.y * BM;

    const int row_ld = tid >> 2;       // 0..127
    const int ch_ld  = tid & 3;        // 16B chunk 0..3

    // Global source pointers, advanced by constant BK per stage
    const __half* Ag = A + (mbase + row_ld) * (size_t)KK + (ch_ld << 3);
    const __half* Bg = Bt + (size_t)(nbase + row_ld) * KK + (ch_ld << 3);
    const uint32_t soff = (uint32_t)row_ld * (SROWH * 2) + ((uint32_t)ch_ld << 4);

    const int r8  = lane & 7;
    const int sel = lane >> 3;
    const uint32_t rowadd = (uint32_t)((sel & 1) << 3);
    const uint32_t kbadd  = (uint32_t)((sel >> 1) << 4);
    uint32_t a_off[2], b_off[2];
    #pragma unroll
    for (int i = 0; i < 2; i++)
        a_off[i] = sbase + (uint32_t)(wm + 16 * i + rowadd + r8) * (SROWH * 2) + kbadd;
    #pragma unroll
    for (int p = 0; p < 2; p++)
        b_off[p] = sbase + (uint32_t)ABUF
                 + (uint32_t)(wn + 16 * p + rowadd + r8) * (SROWH * 2) + kbadd;

    float acc[2][4][4];
    #pragma unroll
    for (int i = 0; i < 2; i++)
        #pragma unroll
        for (int j = 0; j < 4; j++)
            #pragma unroll
            for (int t = 0; t < 4; t++) acc[i][j][t] = 0.f;

    // Stage loader: all offsets compile-time when s is a constant
    #define LOAD_STAGE(s)                                                        \
        do {                                                                     \
            const uint32_t base_ = sbase + (uint32_t)(((s) % NSTAGE) * STAGE_BYTES); \
            cp_async16(base_ + soff, Ag + (s) * BK);                             \
            cp_async16(base_ + ABUF + soff, Bg + (size_t)(s) * BK);              \
            asm volatile("cp.async.commit_group;");                              \
        } while (0)

    LOAD_STAGE(0);
    LOAD_STAGE(1);
    LOAD_STAGE(2);
    LOAD_STAGE(3);

    #pragma unroll
    for (int s = 0; s < NSTAGES_TOT; s++) {
        if      (s + 3 < NSTAGES_TOT) cp_wait<3>();
        else if (s + 2 < NSTAGES_TOT) cp_wait<2>();
        else if (s + 1 < NSTAGES_TOT) cp_wait<1>();
        else                          cp_wait<0>();
        __syncthreads();
        if (s + 4 < NSTAGES_TOT) LOAD_STAGE(s + 4);

        const uint32_t sb = (uint32_t)((s % NSTAGE) * STAGE_BYTES);
        #pragma unroll
        for (int ks = 0; ks < 2; ks++) {
            const uint32_t kb = sb + ((uint32_t)ks << 5);
            uint32_t afr[2][4];
            uint32_t bfr[2][4];
            #pragma unroll
            for (int i = 0; i < 2; i++) ldm_x4(afr[i], a_off[i] + kb);
            #pragma unroll
            for (int p = 0; p < 2; p++) ldm_x4(bfr[p], b_off[p] + kb);
            #pragma unroll
            for (int i = 0; i < 2; i++)
                #pragma unroll
                for (int j = 0; j < 4; j++)
                    mma_f16(acc[i][j], afr[i], bfr[j >> 1][j & 1],
                            bfr[j >> 1][(j & 1) + 2]);
        }
    }
    #undef LOAD_STAGE

    #pragma unroll
    for (int i = 0; i < 2; i++) {
        const size_t row = mbase + wm + i * 16 + qr;
        #pragma unroll
        for (int j = 0; j < 4; j++) {
            const int col = nbase + wn + j * 8 + 2 * qc;
            if (HALF_OUT) {
                __half* Ch = (__half*)Cout;
                *(__half2*)(Ch + row * (size_t)N + col) =
                    __floats2half2_rn(acc[i][j][0], acc[i][j][1]);
                *(__half2*)(Ch + (row + 8) * (size_t)N + col) =
                    __floats2half2_rn(acc[i][j][2], acc[i][j][3]);
            } else {
                float* Cf = (float*)Cout;
                float2 v0 = make_float2(acc[i][j][0], acc[i][j][1]);
                float2 v1 = make_float2(acc[i][j][2], acc[i][j][3]);
                if (bias) {
                    float2 bb = *(const float2*)(bias + col);
                    v0.x += bb.x; v0.y += bb.y;
                    v1.x += bb.x; v1.y += bb.y;
                }
                *(float2*)(Cf + row * (size_t)N + col) = v0;
                *(float2*)(Cf + (row + 8) * (size_t)N + col) = v1;
            }
        }
    }
}

// ---------------------------------------------------------------------------
__global__ void to_half_kernel(const float* __restrict__ in, __half* __restrict__ out, int n4)
{
    int i = blockIdx.x * blockDim.x + threadIdx.x;
    if (i >= n4) return;
    float4 v = ((const float4*)in)[i];
    ((__half2*)out)[i * 2 + 0] = __floats2half2_rn(v.x, v.y);
    ((__half2*)out)[i * 2 + 1] = __floats2half2_rn(v.z, v.w);
}

__global__ void transpose_half_kernel(const float* __restrict__ in, __half* __restrict__ out,
                                      int K, int N)
{
    int i = blockIdx.x * blockDim.x + threadIdx.x;
    if (i >= K * N) return;
    int n = i % N, k = i / N;
    out[(size_t)n * K + k] = __float2half_rn(in[(size_t)k * N + n]);
}

// ---------------------------------------------------------------------------
// TC windowed attention + fused depthwise 3x3 conv(v) + bias (R14, unchanged).
// ---------------------------------------------------------------------------
__global__ __launch_bounds__(128)
void attn_tc_kernel(const __half* __restrict__ qkvh,
                    const float* __restrict__ w_conv,
                    const float* __restrict__ b_conv,
                    __half* __restrict__ yh)
{
    extern __shared__ char sm[];
    const uint32_t sbase = smem_u32(sm);
    const int tid  = threadIdx.x;
    const int wid  = tid >> 5;
    const int lane = tid & 31;
    const int qr = lane >> 2, qc = lane & 3;
    const int r8 = lane & 7, g = lane >> 3;

    int blk = blockIdx.x;
    const int hg = blk % 3; blk /= 3;
    const int w = blk & 63; const int b = blk >> 6;
    const int row0 = (w >> 3) * 7, cpix0 = (w & 7) * 7;
    const int col0 = (hg * 4 + wid) * HD;

    // Main q,k,v tiles: 2352 16B chunks
    for (int it = 0; it < 19; it++) {
        int idx = tid + it * 128;
        if (idx < 2352) {
            int c = idx & 3;
            int r = (idx >> 2) % 49;
            int zt = (idx >> 2) / 49;
            int hh = zt / 3, tz = zt % 3;
            int pix = (row0 + r / 7) * WW + cpix0 + (r % 7);
            const __half* src = qkvh + ((size_t)(b * NN + pix)) * C3
                              + tz * CC + (hg * 4 + hh) * HD + c * 8;
            cp_async16(sbase + (uint32_t)(zt * ATILE + r * 80 + c * 16), src);
        }
    }
    // Conv ring halo: 32 ring pixels x 4 heads x 4 chunks = 512 chunks
    for (int it = 0; it < 4; it++) {
        int chunk = tid + it * 128;
        int c4 = chunk & 3;
        int head = (chunk >> 2) & 3;
        int ridx = chunk >> 4;               // 0..31
        int gr, gc;
        if (ridx < 9)       { gr = 0; gc = ridx; }
        else if (ridx < 18) { gr = 8; gc = ridx - 9; }
        else { int e = ridx - 18; gr = 1 + (e >> 1); gc = (e & 1) ? 8 : 0; }
        int r = row0 - 1 + gr, c = cpix0 - 1 + gc;
        uint32_t dst = sbase + (uint32_t)(RING_OFF + ridx * 256 + head * 64 + c4 * 16);
        if ((unsigned)r < (unsigned)HH && (unsigned)c < (unsigned)WW) {
            cp_async16(dst, qkvh + ((size_t)(b * NN + r * WW + c)) * C3
                             + 2 * CC + (hg * 4 + head) * HD + c4 * 8);
        } else {
            *(uint4*)(sm + RING_OFF + ridx * 256 + head * 64 + c4 * 16) =
                make_uint4(0, 0, 0, 0);
        }
    }
    // Conv weights (fp32) per head: 1152 floats
    for (int it = 0; it < 9; it++) {
        int t = tid + it * 128;
        int head = t / 288, rem = t % 288;
        int k = rem / 32, ch = rem % 32;
        ((float*)(sm + WTS_OFF))[t] = w_conv[k * CC + (hg * 4 + head) * HD + ch];
    }
    // Bias per head: 128 floats
    ((float*)(sm + BCS_OFF))[tid] = b_conv[(hg * 4 + (tid >> 5)) * HD + (tid & 31)];

    asm volatile("cp.async.commit_group;");
    cp_wait<0>();
    __syncthreads();

    const uint32_t QB = sbase + (uint32_t)(wid * AHEAD);
    const uint32_t KB = QB + ATILE;
    const uint32_t VB = QB + 2 * ATILE;
    const char* vtile = sm + wid * AHEAD + 2 * ATILE;
    const char* ring  = sm + RING_OFF;
    const float* wts  = (const float*)(sm + WTS_OFF) + wid * 288;
    const float* bcs  = (const float*)(sm + BCS_OFF) + wid * 32;

    // K fragments (rows clamped to 48; masked cols never used)
    uint32_t Kf[8][2][2];
    #pragma unroll
    for (int up = 0; up < 4; up++)
        #pragma unroll
        for (int s = 0; s < 2; s++) {
            int row = 16 * up + r8 + ((g & 1) << 3);
            if (row > 48) row = 48;
            uint32_t addr = KB + (uint32_t)row * 80u
                          + (uint32_t)(32 * s + ((g >> 1) << 4));
            uint32_t r[4];
            ldm_x4(r, addr);
            Kf[2 * up][s][0] = r[0]; Kf[2 * up][s][1] = r[2];
            Kf[2 * up + 1][s][0] = r[1]; Kf[2 * up + 1][s][1] = r[3];
        }
    // V fragments (trans, rows clamped)
    uint32_t Vf[4][4][2];
    #pragma unroll
    for (int wk = 0; wk < 4; wk++)
        #pragma unroll
        for (int up = 0; up < 2; up++) {
            int row = 16 * wk + r8 + ((g >> 1) << 3);
            if (row > 48) row = 48;
            uint32_t addr = VB + (uint32_t)row * 80u
                          + (uint32_t)(32 * up + ((g & 1) << 4));
            uint32_t r[4];
            ldm_x4_t(r, addr);
            Vf[2 * up][wk][0] = r[0]; Vf[2 * up][wk][1] = r[2];
            Vf[2 * up + 1][wk][0] = r[1]; Vf[2 * up + 1][wk][1] = r[3];
        }

    bool vc0[7], vc1[7];
    #pragma unroll
    for (int u = 0; u < 7; u++) {
        int cb = 8 * u + 2 * qc;
        vc0[u] = cb < WIN;
        vc1[u] = cb + 1 < WIN;
    }

    const float scale = 0.17677669529663687f;

    auto conv_row = [&](int wr, int wc, float cv[4][2]) {
        #pragma unroll
        for (int u = 0; u < 4; u++) {
            float2 bb = *(const float2*)(bcs + 8 * u + 2 * qc);
            cv[u][0] = bb.x; cv[u][1] = bb.y;
        }
        #pragma unroll
        for (int kh = 0; kh < 3; kh++)
            #pragma unroll
            for (int kw = 0; kw < 3; kw++) {
                const int gr = wr + kh, gc = wc + kw;     // 0..8
                const char* vb;
                if ((unsigned)(gr - 1) < 7u && (unsigned)(gc - 1) < 7u) {
                    vb = vtile + ((gr - 1) * 7 + (gc - 1)) * 80;
                } else {
                    int ridx = (gr == 0) ? gc
                             : (gr == 8) ? 9 + gc
                             : 18 + (gr - 1) * 2 + (gc == 8 ? 1 : 0);
                    vb = ring + ridx * 256 + wid * 64;
                }
                const float* wk = wts + (kh * 3 + kw) * 32;
                #pragma unroll
                for (int u = 0; u < 4; u++) {
                    float2 vf = __half22float2(*(const __half2*)(vb + u * 16 + qc * 4));
                    float2 wf = *(const float2*)(wk + 8 * u + 2 * qc);
                    cv[u][0] += vf.x * wf.x;
                    cv[u][1] += vf.y * wf.y;
                }
            }
    };

    #pragma unroll
    for (int t = 0; t < 4; t++) {
        uint32_t Qf[2][4];
        #pragma unroll
        for (int s = 0; s < 2; s++) {
            int row = 16 * t + r8 + ((g & 1) << 3);
            if (row > 48) row = 48;
            uint32_t addr = QB + (uint32_t)row * 80u
                          + (uint32_t)(32 * s + ((g >> 1) << 4));
            ldm_x4(Qf[s], addr);
        }
        float S[7][4];
        #pragma unroll
        for (int u = 0; u < 7; u++) {
            S[u][0] = S[u][1] = S[u][2] = S[u][3] = 0.f;
            mma_f16(S[u], Qf[0], Kf[u][0][0], Kf[u][0][1]);
            mma_f16(S[u], Qf[1], Kf[u][1][0], Kf[u][1][1]);
        }

        const int rr0 = 16 * t + qr;
        const int rr1 = rr0 + 8;
        const bool vr0 = rr0 < WIN, vr1 = rr1 < WIN;

        float m0 = -1e30f, m1 = -1e30f;
        #pragma unroll
        for (int u = 0; u < 7; u++) {
            if (vc0[u]) { m0 = fmaxf(m0, S[u][0]); m1 = fmaxf(m1, S[u][2]); }
            if (vc1[u]) { m0 = fmaxf(m0, S[u][1]); m1 = fmaxf(m1, S[u][3]); }
        }
        #pragma unroll
        for (int o = 1; o <= 2; o <<= 1) {
            m0 = fmaxf(m0, __shfl_xor_sync(0xffffffffu, m0, o));
            m1 = fmaxf(m1, __shfl_xor_sync(0xffffffffu, m1, o));
        }

        uint32_t P[8][2];
        P[7][0] = 0u; P[7][1] = 0u;
        float sum0 = 0.f, sum1 = 0.f;
        #pragma unroll
        for (int u = 0; u < 7; u++) {
            float p0 = 0.f, p1 = 0.f, p2 = 0.f, p3 = 0.f;
            if (vr0) {
                if (vc0[u]) p0 = __expf((S[u][0] - m0) * scale);
                if (vc1[u]) p1 = __expf((S[u][1] - m0) * scale);
            }
            if (vr1) {
                if (vc0[u]) p2 = __expf((S[u][2] - m1) * scale);
                if (vc1[u]) p3 = __expf((S[u][3] - m1) * scale);
            }
            sum0 += p0 + p1;
            sum1 += p2 + p3;
            P[u][0] = h2u(__floats2half2_rn(p0, p1));
            P[u][1] = h2u(__floats2half2_rn(p2, p3));
        }
        #pragma unroll
        for (int o = 1; o <= 2; o <<= 1) {
            sum0 += __shfl_xor_sync(0xffffffffu, sum0, o);
            sum1 += __shfl_xor_sync(0xffffffffu, sum1, o);
        }
        const float is0 = vr0 ? 1.f / sum0 : 0.f;
        const float is1 = vr1 ? 1.f / sum1 : 0.f;

        float O[4][4];
        #pragma unroll
        for (int u = 0; u < 4; u++)
            O[u][0] = O[u][1] = O[u][2] = O[u][3] = 0.f;
        #pragma unroll
        for (int wk = 0; wk < 4; wk++) {
            uint32_t afr[4] = { P[2 * wk][0], P[2 * wk][1],
                                P[2 * wk + 1][0], P[2 * wk + 1][1] };
            #pragma unroll
            for (int u = 0; u < 4; u++)
                mma_f16(O[u], afr, Vf[u][wk][0], Vf[u][wk][1]);
        }

        if (vr0) {
            const int wr = rr0 / 7, wc = rr0 % 7;
            float cv[4][2];
            conv_row(wr, wc, cv);
            int pix = (row0 + wr) * WW + cpix0 + wc;
            __half* base = yh + ((size_t)(b * NN + pix)) * CC + col0;
            #pragma unroll
            for (int u = 0; u < 4; u++)
                *(__half2*)(base + 8 * u + 2 * qc) =
                    __floats2half2_rn(O[u][0] * is0 + cv[u][0],
                                      O[u][1] * is0 + cv[u][1]);
        }
        if (vr1) {
            const int wr = rr1 / 7, wc = rr1 % 7;
            float cv[4][2];
            conv_row(wr, wc, cv);
            int pix = (row0 + wr) * WW + cpix0 + wc;
            __half* base = yh + ((size_t)(b * NN + pix)) * CC + col0;
            #pragma unroll
            for (int u = 0; u < 4; u++)
                *(__half2*)(base + 8 * u + 2 * qc) =
                    __floats2half2_rn(O[u][2] * is1 + cv[u][0],
                                      O[u][3] * is1 + cv[u][1]);
        }
    }
}

// ---------------------------------------------------------------------------
extern "C" void kernel_launch(void* const* d_in, const int* in_sizes, int n_in,
                              void* d_out, int out_size)
{
    const float* x      = (const float*)d_in[0];
    const float* w_qkv  = (const float*)d_in[1];
    const float* w_proj = (const float*)d_in[2];
    const float* b_proj = (const float*)d_in[3];
    const float* w_conv = (const float*)d_in[4];
    const float* b_conv = (const float*)d_in[5];
    float* out = (float*)d_out;

    __half *qkvh_p, *xh_p, *yh_p, *wt1_p, *wt2_p;
    cudaGetSymbolAddress((void**)&qkvh_p, g_qkvh);
    cudaGetSymbolAddress((void**)&xh_p, g_xh);
    cudaGetSymbolAddress((void**)&yh_p, g_yh);
    cudaGetSymbolAddress((void**)&wt1_p, g_wt1);
    cudaGetSymbolAddress((void**)&wt2_p, g_wt2);

    const int gemm_smem = NSTAGE * STAGE_BYTES;  // 102400
    cudaFuncSetAttribute(gemm_f16_kernel<true>,
                         cudaFuncAttributeMaxDynamicSharedMemorySize, gemm_smem);
    cudaFuncSetAttribute(gemm_f16_kernel<false>,
                         cudaFuncAttributeMaxDynamicSharedMemorySize, gemm_smem);
    cudaFuncSetAttribute(attn_tc_kernel,
                         cudaFuncAttributeMaxDynamicSharedMemorySize, ASMEM);

    // 0) fp16 conversions
    {
        int n4 = MROWS * CC / 4;
        to_half_kernel<<<(n4 + 255) / 256, 256>>>(x, xh_p, n4);
        transpose_half_kernel<<<(CC * C3 + 255) / 256, 256>>>(w_qkv, wt1_p, CC, C3);
        transpose_half_kernel<<<(CC * CC + 255) / 256, 256>>>(w_proj, wt2_p, CC, CC);
    }
    // 1) qkvh = x @ w_qkv (fp16 out)
    {
        dim3 grid(C3 / BN, MROWS / BM);
        gemm_f16_kernel<true><<<grid, 512, gemm_smem>>>(xh_p, wt1_p, qkvh_p, nullptr,
                                                        MROWS, C3);
    }
    // 2) TC windowed attention + fused depthwise conv -> yh (fp16)
    attn_tc_kernel<<<BATCH * 64 * 3, 128, ASMEM>>>(qkvh_p, w_conv, b_conv, yh_p);
    // 3) out = yh @ w_proj + b_proj (fp32 out)
    {
        dim3 grid(CC / BN, MROWS / BM);
        gemm_f16_kernel<false><<<grid, 512, gemm_smem>>>(yh_p, wt2_p, out, b_proj,
                                                         MROWS, CC);
    }
}